// round 11
// baseline (speedup 1.0000x reference)
#include <cuda_runtime.h>
#include <math.h>
#include <stdint.h>

#define D_  1024
#define H_  16
#define HD_ 64
#define F_  2816
#define A_  64
#define P_  30
#define NB_ 32
#define B_  4
#define L_  1024
#define LK_ 1054            // P_ + L_
#define M_  4096            // B_ * L_

// ---------------- scratch (device globals; no runtime allocation) ----------------
__device__ float g_xn[M_ * D_];
__device__ float g_q [M_ * D_];
__device__ float g_kc[B_ * LK_ * D_];
__device__ float g_vc[B_ * LK_ * D_];
__device__ float g_o [M_ * D_];
__device__ float g_x [M_ * D_];
__device__ float g_y [M_ * D_];
__device__ float g_h0[(size_t)M_ * F_];
__device__ float g_h1[(size_t)M_ * F_];
__device__ float g_az[B_ * L_ * A_];
__device__ float g_bt[H_ * L_];
__device__ float g_wtf[21757952];      // tf32-rounded weights + encoded

// float offsets into g_wtf
#define WQ0o  0
#define WK0o  1048576
#define WV0o  2097152
#define WO0o  3145728
#define WQ1o  4194304
#define WK1o  5242880
#define WV1o  6291456
#define WO1o  7340032
#define WI0o  8388608
#define WI1o  11272192
#define WOMo  14155776
#define AWDo  17039360
#define AWUo  17301504
#define ENCo  17563648

// ---------------- helpers ----------------
__device__ __forceinline__ float gelu_f(float x) {
    const float c = 0.7978845608028654f;       // sqrt(2/pi)
    float t = tanhf(c * (x + 0.044715f * x * x * x));
    return 0.5f * x * (1.0f + t);
}

__device__ __forceinline__ unsigned f2tf(float f) {
    unsigned u;
    asm("cvt.rna.tf32.f32 %0, %1;" : "=r"(u) : "f"(f));
    return u;
}
__device__ __forceinline__ float roundtf(float f) { return __uint_as_float(f2tf(f)); }

__device__ __forceinline__ void mma8(float* c, const unsigned* a, unsigned b0, unsigned b1) {
    asm volatile(
        "mma.sync.aligned.m16n8k8.row.col.f32.tf32.tf32.f32 "
        "{%0,%1,%2,%3},{%4,%5,%6,%7},{%8,%9},{%0,%1,%2,%3};"
        : "+f"(c[0]), "+f"(c[1]), "+f"(c[2]), "+f"(c[3])
        : "r"(a[0]), "r"(a[1]), "r"(a[2]), "r"(a[3]), "r"(b0), "r"(b1));
}

__device__ __forceinline__ void ldsm4(unsigned& r0, unsigned& r1, unsigned& r2, unsigned& r3,
                                      uint32_t addr) {
    asm volatile("ldmatrix.sync.aligned.m8n8.x4.shared.b16 {%0,%1,%2,%3}, [%4];"
                 : "=r"(r0), "=r"(r1), "=r"(r2), "=r"(r3) : "r"(addr));
}

__device__ __forceinline__ uint32_t smem_u32(const void* p) {
    uint32_t a;
    asm("{ .reg .u64 t; cvta.to.shared.u64 t, %1; cvt.u32.u64 %0, t; }" : "=r"(a) : "l"(p));
    return a;
}

// ---------------- weight/encoded tf32 conversion (flattened, one launch) ----------------
struct ConvArgs { const float4* src[14]; };
#define CONV_TOT4 5439488

__global__ void conv_kernel(ConvArgs a, float4* __restrict__ dst) {
    static const int cum[15] = {0, 262144, 524288, 786432, 1048576, 1310720, 1572864,
                                1835008, 2097152, 2818048, 3538944, 4259840, 4325376,
                                4390912, 5439488};
    int t = blockIdx.x * 256 + threadIdx.x;
    if (t >= CONV_TOT4) return;
    int j = 0;
    #pragma unroll
    for (int k = 1; k < 14; ++k) if (t >= cum[k]) j = k;
    float4 v = a.src[j][t - cum[j]];
    v.x = roundtf(v.x); v.y = roundtf(v.y); v.z = roundtf(v.z); v.w = roundtf(v.w);
    dst[t] = v;
}

// ---------------- rmsnorm (tf32-rounded output) ----------------
__global__ void rmsnorm_kernel(const float* __restrict__ x,
                               const float* __restrict__ sc,
                               float* __restrict__ out) {
    int row = blockIdx.x;
    int t = threadIdx.x;
    const float4* xr = (const float4*)(x + (size_t)row * D_);
    float4 v = xr[t];
    float ss = v.x * v.x + v.y * v.y + v.z * v.z + v.w * v.w;
    #pragma unroll
    for (int o = 16; o; o >>= 1) ss += __shfl_xor_sync(0xffffffffu, ss, o);
    __shared__ float sred[8];
    if ((t & 31) == 0) sred[t >> 5] = ss;
    __syncthreads();
    if (t < 8) {
        float s2 = sred[t];
        #pragma unroll
        for (int o = 4; o; o >>= 1) s2 += __shfl_xor_sync(0xffu, s2, o);
        if (t == 0) sred[0] = s2;
    }
    __syncthreads();
    float inv = rsqrtf(sred[0] * (1.0f / D_) + 1e-6f);
    float4 sv = ((const float4*)sc)[t];
    float4 ov = make_float4(roundtf(v.x * inv * sv.x), roundtf(v.y * inv * sv.y),
                            roundtf(v.z * inv * sv.z), roundtf(v.w * inv * sv.w));
    ((float4*)(out + (size_t)row * D_))[t] = ov;
}

// ---------------- tf32 tensor-core GEMM (LDSM A + LDSM B via n-major B tile) -----------
// Operands pre-rounded to tf32 (RNA). C = alpha*A*B (+bias)(gelu)(*mulin)
// (+residual)(+=C)(round_out). A[M,K], B[K,N] row-major. M mult 128, K mult 16.
#define GBM 128
#define GBN 128
#define GBK 16
#define ASTR 20
#define BPITCH 20

__global__ __launch_bounds__(256, 2)
void gemm_tc_kernel(const float* __restrict__ A, const float* __restrict__ Bm,
                    float* __restrict__ C, int M, int N, int K,
                    float alpha,
                    const float* __restrict__ bias,
                    const float* __restrict__ mulin,
                    const float* __restrict__ residual,
                    int do_gelu, int accumulate, int round_out, int kv_pad, int seg_rows,
                    long long sA, long long sB, long long sC,
                    long long sBias, long long sRes) {
    int z = blockIdx.z;
    A  += (size_t)z * sA;
    Bm += (size_t)z * sB;
    C  += (size_t)z * sC;
    if (bias)     bias     += (size_t)z * sBias;
    if (residual) residual += (size_t)z * sRes;

    __shared__ __align__(16) float As[2][GBM * ASTR];
    __shared__ __align__(16) float Bs[2][GBN * BPITCH];   // n-major: Bs[n][k]

    int tid  = threadIdx.x;
    int lane = tid & 31;
    int wid  = tid >> 5;
    int grpr = lane >> 2;
    int grpc = lane & 3;
    int warp_m = (wid & 1) * 64;
    int warp_n = (wid >> 1) * 32;
    int bm = blockIdx.y * GBM;
    int bn = blockIdx.x * GBN;

    // A loader: rows ar, ar+64; float4 along k
    int ar = tid >> 2;
    int ac = (tid & 3) * 4;
    // B loader: n-major; thread handles (n = tid&127, k blocks kh and kh+8)
    int nB = tid & 127;
    int kh = (tid >> 7) * 4;
    int bok = (bn + nB < N);
    const float* Bp = Bm + (bok ? bn + nB : 0);

    // LDSM lane offsets
    uint32_t asBase = smem_u32(&As[0][0]);
    uint32_t aLane  = asBase + (((lane & 15) * ASTR + (lane >> 4) * 4) + warp_m * ASTR) * 4u;
    uint32_t bsBase = smem_u32(&Bs[0][0]);
    uint32_t bLane  = bsBase + (((warp_n + (lane & 7) + ((lane >> 4) * 8)) * BPITCH
                                 + ((lane >> 3) & 1) * 4)) * 4u;

    float acc[4][4][4];
    #pragma unroll
    for (int i = 0; i < 4; ++i)
        #pragma unroll
        for (int j = 0; j < 4; ++j)
            #pragma unroll
            for (int k = 0; k < 4; ++k) acc[i][j][k] = 0.0f;

    int ntiles = K / GBK;
    float4 aR0, aR1, bR0, bR1;

    // prefetch tile 0
    {
        aR0 = *(const float4*)(A + (size_t)(bm + ar) * K + ac);
        aR1 = *(const float4*)(A + (size_t)(bm + ar + 64) * K + ac);
        if (bok) {
            bR0.x = Bp[(size_t)(kh + 0) * N]; bR0.y = Bp[(size_t)(kh + 1) * N];
            bR0.z = Bp[(size_t)(kh + 2) * N]; bR0.w = Bp[(size_t)(kh + 3) * N];
            bR1.x = Bp[(size_t)(kh + 8) * N]; bR1.y = Bp[(size_t)(kh + 9) * N];
            bR1.z = Bp[(size_t)(kh + 10) * N]; bR1.w = Bp[(size_t)(kh + 11) * N];
        } else { bR0 = make_float4(0,0,0,0); bR1 = bR0; }
        float* ap = &As[0][ar * ASTR + ac];
        ap[0]=aR0.x; ap[1]=aR0.y; ap[2]=aR0.z; ap[3]=aR0.w;
        float* ap2 = &As[0][(ar + 64) * ASTR + ac];
        ap2[0]=aR1.x; ap2[1]=aR1.y; ap2[2]=aR1.z; ap2[3]=aR1.w;
        *(float4*)&Bs[0][nB * BPITCH + kh] = bR0;
        *(float4*)&Bs[0][nB * BPITCH + kh + 8] = bR1;
    }
    __syncthreads();

    int buf = 0;
    for (int kt = 0; kt < ntiles; ++kt) {
        int knext = (kt + 1) * GBK;
        if (kt + 1 < ntiles) {
            aR0 = *(const float4*)(A + (size_t)(bm + ar) * K + knext + ac);
            aR1 = *(const float4*)(A + (size_t)(bm + ar + 64) * K + knext + ac);
            if (bok) {
                const float* Bn = Bp + (size_t)knext * N;
                bR0.x = Bn[(size_t)(kh + 0) * N]; bR0.y = Bn[(size_t)(kh + 1) * N];
                bR0.z = Bn[(size_t)(kh + 2) * N]; bR0.w = Bn[(size_t)(kh + 3) * N];
                bR1.x = Bn[(size_t)(kh + 8) * N]; bR1.y = Bn[(size_t)(kh + 9) * N];
                bR1.z = Bn[(size_t)(kh + 10) * N]; bR1.w = Bn[(size_t)(kh + 11) * N];
            }
        }
        // compute on buf
        uint32_t aBufLane = aLane + (uint32_t)buf * sizeof(As[0]);
        uint32_t bBufLane = bLane + (uint32_t)buf * sizeof(Bs[0]);
        #pragma unroll
        for (int ks = 0; ks < 2; ++ks) {
            unsigned af[4][4];
            #pragma unroll
            for (int ma = 0; ma < 4; ++ma)
                ldsm4(af[ma][0], af[ma][1], af[ma][2], af[ma][3],
                      aBufLane + (uint32_t)((ma * 16 * ASTR + ks * 8) * 4));
            #pragma unroll
            for (int p = 0; p < 2; ++p) {
                unsigned kb[4];
                ldsm4(kb[0], kb[1], kb[2], kb[3],
                      bBufLane + (uint32_t)((p * 16 * BPITCH + ks * 8) * 4));
                #pragma unroll
                for (int ma = 0; ma < 4; ++ma) {
                    mma8(acc[ma][2 * p + 0], af[ma], kb[0], kb[1]);
                    mma8(acc[ma][2 * p + 1], af[ma], kb[2], kb[3]);
                }
            }
        }
        if (kt + 1 < ntiles) {
            int nb = buf ^ 1;
            float* ap = &As[nb][ar * ASTR + ac];
            ap[0]=aR0.x; ap[1]=aR0.y; ap[2]=aR0.z; ap[3]=aR0.w;
            float* ap2 = &As[nb][(ar + 64) * ASTR + ac];
            ap2[0]=aR1.x; ap2[1]=aR1.y; ap2[2]=aR1.z; ap2[3]=aR1.w;
            *(float4*)&Bs[nb][nB * BPITCH + kh] = bR0;
            *(float4*)&Bs[nb][nB * BPITCH + kh + 8] = bR1;
            __syncthreads();
            buf = nb;
        }
    }

    // epilogue: element pairs at (m, n), (m, n+1)
    #pragma unroll
    for (int ma = 0; ma < 4; ++ma) {
        #pragma unroll
        for (int na = 0; na < 4; ++na) {
            int n = bn + warp_n + na * 8 + 2 * grpc;
            if (n >= N) continue;
            #pragma unroll
            for (int half = 0; half < 2; ++half) {
                int m = bm + warp_m + ma * 16 + grpr + half * 8;
                float v0 = alpha * acc[ma][na][half * 2 + 0];
                float v1 = alpha * acc[ma][na][half * 2 + 1];
                if (bias) { v0 += bias[n]; v1 += bias[n + 1]; }
                if (do_gelu) { v0 = gelu_f(v0); v1 = gelu_f(v1); }
                if (mulin) {
                    float2 mv = *(const float2*)(mulin + (size_t)m * N + n);
                    v0 *= mv.x; v1 *= mv.y;
                }
                if (residual) {
                    float2 rv = *(const float2*)(residual + (size_t)m * N + n);
                    v0 += rv.x; v1 += rv.y;
                }
                long long orow = m;
                if (kv_pad) orow = (long long)m + (long long)kv_pad * (m / seg_rows + 1);
                float* cp = C + (size_t)orow * N + n;
                if (accumulate) {
                    float2 cv = *(const float2*)cp;
                    v0 += cv.x; v1 += cv.y;
                }
                if (round_out) { v0 = roundtf(v0); v1 = roundtf(v1); }
                *(float2*)cp = make_float2(v0, v1);
            }
        }
    }
}

// ---------------- relative position bias table ----------------
__global__ void biastab_kernel(const float* __restrict__ relpos, float* __restrict__ tab) {
    int idx = blockIdx.x * 256 + threadIdx.x;
    if (idx >= H_ * L_) return;
    int h = idx / L_, rel = idx % L_;
    int bucket;
    if (rel < 16) {
        bucket = rel;
    } else {
        float lg = logf((float)rel * (1.0f / 16.0f)) * (16.0f / 2.0794415416798357f);
        bucket = 16 + (int)lg;
        if (bucket > 31) bucket = 31;
    }
    tab[idx] = relpos[h * NB_ + bucket];
}

// ---------------- prefix KV copy (tf32-rounded) ----------------
__global__ void prefix_kernel(const float* __restrict__ pk, const float* __restrict__ pv,
                              float* __restrict__ kc, float* __restrict__ vc, int sel) {
    int b = blockIdx.y;
    int i = blockIdx.x * 256 + threadIdx.x;
    if (i >= P_ * D_) return;
    size_t src = ((size_t)(b * 2 + sel)) * (P_ * D_) + i;
    size_t dst = (size_t)b * LK_ * D_ + i;
    kc[dst] = roundtf(pk[src]);
    vc[dst] = roundtf(pv[src]);
}

// ---------------- tensor-core flash attention (LDSM for Q/K/P fragments) --------------
#define ATTN_SMEM_TC ((64 * 68 + 64 * 72 + 64 * 68) * 4 + L_ * 4)

template <bool CAUSAL>
__global__ __launch_bounds__(128)
void attn_tc_kernel(const float* __restrict__ Q, const float* __restrict__ Kc,
                    const float* __restrict__ Vc, float* __restrict__ O,
                    const float* __restrict__ btab) {
    extern __shared__ __align__(16) unsigned smu[];
    unsigned* Ks = smu;                      // [64][68]
    unsigned* Vs = Ks + 64 * 68;             // [64][72]
    unsigned* Ps = Vs + 64 * 72;             // [64][68]
    float* bsh = (float*)(Ps + 64 * 68);     // [1024]

    int q0 = blockIdx.x * 64;
    int h  = blockIdx.y;
    int b  = blockIdx.z;
    int tid  = threadIdx.x;
    int w    = tid >> 5;
    int lane = tid & 31;
    int grpr = lane >> 2;
    int grpc = lane & 3;

    const float* Qb = Q  + (size_t)(b * L_)  * D_ + h * HD_;
    const float* Kb = Kc + (size_t)(b * LK_) * D_ + h * HD_;
    const float* Vb = Vc + (size_t)(b * LK_) * D_ + h * HD_;

    uint32_t ksU = smem_u32(Ks);
    uint32_t psU = smem_u32(Ps);
    uint32_t laneA = (((lane & 15) * 68 + (lane >> 4) * 4)) * 4u;
    uint32_t laneK = ((((lane & 7) + (lane >> 4) * 8) * 68 + ((lane >> 3) & 1) * 4)) * 4u;

    for (int i = tid; i < 64 * 16; i += 128) {
        int r = i >> 4, c4 = i & 15;
        float4 v = *(const float4*)(Qb + (size_t)(q0 + r) * D_ + c4 * 4);
        *(float4*)&Ks[r * 68 + c4 * 4] = v;
    }
    if (CAUSAL) {
        for (int i = tid; i < L_; i += 128) bsh[i] = btab[h * L_ + i];
    }
    __syncthreads();

    unsigned qa[8][4];
    {
        uint32_t qBase = ksU + laneA + (uint32_t)(w * 16 * 68 * 4);
        #pragma unroll
        for (int ks = 0; ks < 8; ++ks)
            ldsm4(qa[ks][0], qa[ks][1], qa[ks][2], qa[ks][3], qBase + ks * 32u);
    }

    float m0r = -1e30f, m1r = -1e30f, l0 = 0.0f, l1 = 0.0f;
    float oacc[8][4];
    #pragma unroll
    for (int na = 0; na < 8; ++na)
        #pragma unroll
        for (int k = 0; k < 4; ++k) oacc[na][k] = 0.0f;

    int r0g = q0 + w * 16 + grpr;
    int r1g = r0g + 8;

    int ntiles = (LK_ + 63) / 64;
    if (CAUSAL) {
        int need = blockIdx.x + 2;
        if (need < ntiles) ntiles = need;
    }

    for (int kt = 0; kt < ntiles; ++kt) {
        int k0 = kt * 64;
        __syncthreads();
        for (int i = tid; i < 64 * 16; i += 128) {
            int r = i >> 4, c4 = i & 15;
            int j = k0 + r;
            float4 kv, vv;
            if (j < LK_) {
                kv = *(const float4*)(Kb + (size_t)j * D_ + c4 * 4);
                vv = *(const float4*)(Vb + (size_t)j * D_ + c4 * 4);
            } else {
                kv = make_float4(0.f, 0.f, 0.f, 0.f);
                vv = kv;
            }
            *(float4*)&Ks[r * 68 + c4 * 4] = kv;
            *(float4*)&Vs[r * 72 + c4 * 4] = vv;
        }
        __syncthreads();

        float sacc[8][4];
        #pragma unroll
        for (int na = 0; na < 8; ++na)
            #pragma unroll
            for (int k = 0; k < 4; ++k) sacc[na][k] = 0.0f;
        uint32_t kBase = ksU + laneK;
        #pragma unroll
        for (int ks = 0; ks < 8; ++ks) {
            #pragma unroll
            for (int nap = 0; nap < 4; ++nap) {
                unsigned kb[4];
                ldsm4(kb[0], kb[1], kb[2], kb[3],
                      kBase + (uint32_t)((nap * 16 * 68 + ks * 8) * 4));
                mma8(sacc[2 * nap + 0], qa[ks], kb[0], kb[1]);
                mma8(sacc[2 * nap + 1], qa[ks], kb[2], kb[3]);
            }
        }

        float rm0 = -1e30f, rm1 = -1e30f;
        #pragma unroll
        for (int na = 0; na < 8; ++na) {
            int j0 = k0 + na * 8 + 2 * grpc;
            int j1 = j0 + 1;
            if (CAUSAL) {
                if (j0 >= P_) {
                    int kp = j0 - P_;
                    if (kp > r0g) sacc[na][0] = -1e30f; else sacc[na][0] += bsh[r0g - kp];
                    if (kp > r1g) sacc[na][2] = -1e30f; else sacc[na][2] += bsh[r1g - kp];
                }
                if (j1 >= P_) {
                    int kp = j1 - P_;
                    if (kp > r0g) sacc[na][1] = -1e30f; else sacc[na][1] += bsh[r0g - kp];
                    if (kp > r1g) sacc[na][3] = -1e30f; else sacc[na][3] += bsh[r1g - kp];
                }
            } else {
                if (j0 >= LK_) { sacc[na][0] = -1e30f; sacc[na][2] = -1e30f; }
                if (j1 >= LK_) { sacc[na][1] = -1e30f; sacc[na][3] = -1e30f; }
            }
            rm0 = fmaxf(rm0, fmaxf(sacc[na][0], sacc[na][1]));
            rm1 = fmaxf(rm1, fmaxf(sacc[na][2], sacc[na][3]));
        }
        rm0 = fmaxf(rm0, __shfl_xor_sync(0xffffffffu, rm0, 1));
        rm0 = fmaxf(rm0, __shfl_xor_sync(0xffffffffu, rm0, 2));
        rm1 = fmaxf(rm1, __shfl_xor_sync(0xffffffffu, rm1, 1));
        rm1 = fmaxf(rm1, __shfl_xor_sync(0xffffffffu, rm1, 2));

        float mn0 = fmaxf(m0r, rm0);
        float mn1 = fmaxf(m1r, rm1);
        float cf0 = __expf(m0r - mn0);
        float cf1 = __expf(m1r - mn1);
        l0 *= cf0; l1 *= cf1;
        m0r = mn0; m1r = mn1;
        #pragma unroll
        for (int na = 0; na < 8; ++na) {
            oacc[na][0] *= cf0; oacc[na][1] *= cf0;
            oacc[na][2] *= cf1; oacc[na][3] *= cf1;
        }

        float ps0 = 0.0f, ps1 = 0.0f;
        int pr = w * 16 + grpr;
        #pragma unroll
        for (int na = 0; na < 8; ++na) {
            float p0 = __expf(sacc[na][0] - mn0);
            float p1 = __expf(sacc[na][1] - mn0);
            float p2 = __expf(sacc[na][2] - mn1);
            float p3 = __expf(sacc[na][3] - mn1);
            ps0 += p0 + p1;
            ps1 += p2 + p3;
            uint2 u01; u01.x = f2tf(p0); u01.y = f2tf(p1);
            uint2 u23; u23.x = f2tf(p2); u23.y = f2tf(p3);
            *(uint2*)&Ps[pr * 68 + na * 8 + 2 * grpc]       = u01;
            *(uint2*)&Ps[(pr + 8) * 68 + na * 8 + 2 * grpc] = u23;
        }
        ps0 += __shfl_xor_sync(0xffffffffu, ps0, 1);
        ps0 += __shfl_xor_sync(0xffffffffu, ps0, 2);
        ps1 += __shfl_xor_sync(0xffffffffu, ps1, 1);
        ps1 += __shfl_xor_sync(0xffffffffu, ps1, 2);
        l0 += ps0; l1 += ps1;

        __syncwarp();

        uint32_t pBase = psU + laneA + (uint32_t)(w * 16 * 68 * 4);
        #pragma unroll
        for (int ks = 0; ks < 8; ++ks) {
            unsigned pa[4];
            ldsm4(pa[0], pa[1], pa[2], pa[3], pBase + ks * 32u);
            #pragma unroll
            for (int na = 0; na < 8; ++na) {
                unsigned b0 = Vs[(ks * 8 + grpc) * 72 + na * 8 + grpr];
                unsigned b1 = Vs[(ks * 8 + 4 + grpc) * 72 + na * 8 + grpr];
                mma8(oacc[na], pa, b0, b1);
            }
        }
    }

    float inv0 = 1.0f / l0;
    float inv1 = 1.0f / l1;
    float* Ob = O + (size_t)(b * L_) * D_ + h * HD_;
    int qr0 = q0 + w * 16 + grpr;
    #pragma unroll
    for (int na = 0; na < 8; ++na) {
        int d = na * 8 + 2 * grpc;
        *(float2*)(Ob + (size_t)qr0 * D_ + d) =
            make_float2(roundtf(oacc[na][0] * inv0), roundtf(oacc[na][1] * inv0));
        *(float2*)(Ob + (size_t)(qr0 + 8) * D_ + d) =
            make_float2(roundtf(oacc[na][2] * inv1), roundtf(oacc[na][3] * inv1));
    }
}

// ---------------- host side ----------------
static void gemm(const float* A, const float* Bm, float* C, int M, int N, int K,
                 float alpha, const float* bias, const float* mulin,
                 const float* residual,
                 int do_gelu, int accumulate, int round_out, int kv_pad, int seg_rows,
                 long long sA, long long sB, long long sC,
                 long long sBias, long long sRes, int batches) {
    dim3 grid((N + GBN - 1) / GBN, (M + GBM - 1) / GBM, batches);
    gemm_tc_kernel<<<grid, 256>>>(A, Bm, C, M, N, K, alpha, bias, mulin, residual,
                                  do_gelu, accumulate, round_out, kv_pad, seg_rows,
                                  sA, sB, sC, sBias, sRes);
}

extern "C" void kernel_launch(void* const* d_in, const int* in_sizes, int n_in,
                              void* d_out, int out_size) {
    const float* inputs  = (const float*)d_in[0];
    const float* encoded = (const float*)d_in[1];
    const float* awd     = (const float*)d_in[2];
    const float* awu     = (const float*)d_in[3];
    const float* abd     = (const float*)d_in[4];
    const float* abu     = (const float*)d_in[5];
    const float* pk      = (const float*)d_in[6];
    const float* pv      = (const float*)d_in[7];
    const float* ln1     = (const float*)d_in[8];
    const float* ln2     = (const float*)d_in[9];
    const float* ln3     = (const float*)d_in[10];
    const float* sa_wq   = (const float*)d_in[11];
    const float* sa_wk   = (const float*)d_in[12];
    const float* sa_wv   = (const float*)d_in[13];
    const float* sa_wo   = (const float*)d_in[14];
    const float* ca_wq   = (const float*)d_in[15];
    const float* ca_wk   = (const float*)d_in[16];
    const float* ca_wv   = (const float*)d_in[17];
    const float* ca_wo   = (const float*)d_in[18];
    const float* relpos  = (const float*)d_in[19];
    const float* wi0     = (const float*)d_in[20];
    const float* wi1     = (const float*)d_in[21];
    const float* wo      = (const float*)d_in[22];
    float* out = (float*)d_out;

    float *xn, *q, *kc, *vc, *o, *x, *y, *h0, *h1, *az, *bt, *wtf;
    cudaGetSymbolAddress((void**)&xn, g_xn);
    cudaGetSymbolAddress((void**)&q,  g_q);
    cudaGetSymbolAddress((void**)&kc, g_kc);
    cudaGetSymbolAddress((void**)&vc, g_vc);
    cudaGetSymbolAddress((void**)&o,  g_o);
    cudaGetSymbolAddress((void**)&x,  g_x);
    cudaGetSymbolAddress((void**)&y,  g_y);
    cudaGetSymbolAddress((void**)&h0, g_h0);
    cudaGetSymbolAddress((void**)&h1, g_h1);
    cudaGetSymbolAddress((void**)&az, g_az);
    cudaGetSymbolAddress((void**)&bt, g_bt);
    cudaGetSymbolAddress((void**)&wtf, g_wtf);

    cudaFuncSetAttribute(attn_tc_kernel<true>,  cudaFuncAttributeMaxDynamicSharedMemorySize, ATTN_SMEM_TC);
    cudaFuncSetAttribute(attn_tc_kernel<false>, cudaFuncAttributeMaxDynamicSharedMemorySize, ATTN_SMEM_TC);

    // ---- convert weights + encoded to tf32 (one pass) ----
    ConvArgs ca;
    ca.src[0]  = (const float4*)sa_wq;  ca.src[1]  = (const float4*)sa_wk;
    ca.src[2]  = (const float4*)sa_wv;  ca.src[3]  = (const float4*)sa_wo;
    ca.src[4]  = (const float4*)ca_wq;  ca.src[5]  = (const float4*)ca_wk;
    ca.src[6]  = (const float4*)ca_wv;  ca.src[7]  = (const float4*)ca_wo;
    ca.src[8]  = (const float4*)wi0;    ca.src[9]  = (const float4*)wi1;
    ca.src[10] = (const float4*)wo;     ca.src[11] = (const float4*)awd;
    ca.src[12] = (const float4*)awu;    ca.src[13] = (const float4*)encoded;
    conv_kernel<<<(CONV_TOT4 + 255) / 256, 256>>>(ca, (float4*)wtf);

    const float qscale = 0.125f;   // HD^-0.5
    const float* enc_tf = wtf + ENCo;

    // ---- self attention ----
    rmsnorm_kernel<<<M_, 256>>>(inputs, ln1, xn);
    gemm(xn, wtf + WQ0o, q,  M_, D_, D_, qscale, 0, 0, 0, 0, 0, 1, 0, 0,  0, 0, 0, 0, 0, 1);
    gemm(xn, wtf + WK0o, kc, M_, D_, D_, 1.0f,   0, 0, 0, 0, 0, 1, P_, L_, 0, 0, 0, 0, 0, 1);
    gemm(xn, wtf + WV0o, vc, M_, D_, D_, 1.0f,   0, 0, 0, 0, 0, 1, P_, L_, 0, 0, 0, 0, 0, 1);
    prefix_kernel<<<dim3((P_ * D_ + 255) / 256, B_), 256>>>(pk, pv, kc, vc, 0);
    biastab_kernel<<<(H_ * L_ + 255) / 256, 256>>>(relpos, bt);
    attn_tc_kernel<true><<<dim3(L_ / 64, H_, B_), 128, ATTN_SMEM_TC>>>(q, kc, vc, o, bt);
    gemm(o, wtf + WO0o, x, M_, D_, D_, 1.0f, 0, 0, inputs, 0, 0, 0, 0, 0, 0, 0, 0, 0, 0, 1);

    // ---- cross attention ----
    rmsnorm_kernel<<<M_, 256>>>(x, ln2, xn);
    gemm(xn,     wtf + WQ1o, q,  M_, D_, D_, qscale, 0, 0, 0, 0, 0, 1, 0, 0,  0, 0, 0, 0, 0, 1);
    gemm(enc_tf, wtf + WK1o, kc, M_, D_, D_, 1.0f,   0, 0, 0, 0, 0, 1, P_, L_, 0, 0, 0, 0, 0, 1);
    gemm(enc_tf, wtf + WV1o, vc, M_, D_, D_, 1.0f,   0, 0, 0, 0, 0, 1, P_, L_, 0, 0, 0, 0, 0, 1);
    prefix_kernel<<<dim3((P_ * D_ + 255) / 256, B_), 256>>>(pk, pv, kc, vc, 1);
    attn_tc_kernel<false><<<dim3(L_ / 64, H_, B_), 128, ATTN_SMEM_TC>>>(q, kc, vc, o, 0);
    gemm(o, wtf + WO1o, y, M_, D_, D_, 1.0f, 0, 0, x, 0, 0, 0, 0, 0, 0, 0, 0, 0, 0, 1);

    // ---- MLP + adapter (gate fused into wi1 epilogue) ----
    rmsnorm_kernel<<<M_, 256>>>(y, ln3, xn);   // xn = lz (tf32-rounded)
    gemm(xn, wtf + WI0o, h0, M_, F_, D_, 1.0f, 0, 0, 0, 1, 0, 0, 0, 0, 0, 0, 0, 0, 0, 1);  // h0 = gelu(lz@wi0)
    gemm(xn, wtf + WI1o, h1, M_, F_, D_, 1.0f, 0, h0, 0, 0, 0, 1, 0, 0, 0, 0, 0, 0, 0, 1); // h1 = (lz@wi1)*h0 (rounded)
    gemm(h1, wtf + WOMo, out, M_, D_, F_, 1.0f, 0, 0, y, 0, 0, 0, 0, 0, 0, 0, 0, 0, 0, 1);

    // adapter: az = gelu(lz @ wd + bd) (rounded);  out += az @ wu + bu
    gemm(xn, wtf + AWDo, az, L_, A_, D_, 1.0f, abd, 0, 0, 1, 0, 1, 0, 0,
         (long long)L_ * D_, (long long)D_ * A_, (long long)L_ * A_, A_, 0, B_);
    gemm(az, wtf + AWUo, out, L_, D_, A_, 1.0f, abu, 0, 0, 0, 1, 0, 0, 0,
         (long long)L_ * A_, (long long)A_ * D_, (long long)L_ * D_, D_, 0, B_);
}

// round 12
// speedup vs baseline: 1.0365x; 1.0365x over previous
#include <cuda_runtime.h>
#include <math.h>
#include <stdint.h>

#define D_  1024
#define H_  16
#define HD_ 64
#define F_  2816
#define A_  64
#define P_  30
#define NB_ 32
#define B_  4
#define L_  1024
#define LK_ 1054            // P_ + L_
#define M_  4096            // B_ * L_

// ---------------- scratch (device globals; no runtime allocation) ----------------
__device__ float g_xn[M_ * D_];
__device__ float g_q [M_ * D_];
__device__ float g_kc[B_ * LK_ * D_];
__device__ float g_vc[B_ * LK_ * D_];
__device__ float g_o [M_ * D_];
__device__ float g_x [M_ * D_];
__device__ float g_y [M_ * D_];
__device__ float g_h0[(size_t)M_ * F_];
__device__ float g_h1[(size_t)M_ * F_];
__device__ float g_az[B_ * L_ * A_];
__device__ float g_bt[H_ * L_];
__device__ float g_wtf[21757952];      // tf32-rounded weights + encoded

// float offsets into g_wtf
#define WQ0o  0
#define WK0o  1048576
#define WV0o  2097152
#define WO0o  3145728
#define WQ1o  4194304
#define WK1o  5242880
#define WV1o  6291456
#define WO1o  7340032
#define WI0o  8388608
#define WI1o  11272192
#define WOMo  14155776
#define AWDo  17039360
#define AWUo  17301504
#define ENCo  17563648

// ---------------- helpers ----------------
__device__ __forceinline__ float gelu_f(float x) {
    const float c = 0.7978845608028654f;       // sqrt(2/pi)
    float t = tanhf(c * (x + 0.044715f * x * x * x));
    return 0.5f * x * (1.0f + t);
}

__device__ __forceinline__ unsigned f2tf(float f) {
    unsigned u;
    asm("cvt.rna.tf32.f32 %0, %1;" : "=r"(u) : "f"(f));
    return u;
}
__device__ __forceinline__ float roundtf(float f) { return __uint_as_float(f2tf(f)); }

__device__ __forceinline__ void mma8(float* c, const unsigned* a, unsigned b0, unsigned b1) {
    asm volatile(
        "mma.sync.aligned.m16n8k8.row.col.f32.tf32.tf32.f32 "
        "{%0,%1,%2,%3},{%4,%5,%6,%7},{%8,%9},{%0,%1,%2,%3};"
        : "+f"(c[0]), "+f"(c[1]), "+f"(c[2]), "+f"(c[3])
        : "r"(a[0]), "r"(a[1]), "r"(a[2]), "r"(a[3]), "r"(b0), "r"(b1));
}

__device__ __forceinline__ void ldsm4(unsigned& r0, unsigned& r1, unsigned& r2, unsigned& r3,
                                      uint32_t addr) {
    asm volatile("ldmatrix.sync.aligned.m8n8.x4.shared.b16 {%0,%1,%2,%3}, [%4];"
                 : "=r"(r0), "=r"(r1), "=r"(r2), "=r"(r3) : "r"(addr));
}

__device__ __forceinline__ uint32_t smem_u32(const void* p) {
    uint32_t a;
    asm("{ .reg .u64 t; cvta.to.shared.u64 t, %1; cvt.u32.u64 %0, t; }" : "=r"(a) : "l"(p));
    return a;
}

// ---------------- weight/encoded tf32 conversion (flattened, one launch) ----------------
struct ConvArgs { const float4* src[14]; };
#define CONV_TOT4 5439488

__global__ void conv_kernel(ConvArgs a, float4* __restrict__ dst) {
    static const int cum[15] = {0, 262144, 524288, 786432, 1048576, 1310720, 1572864,
                                1835008, 2097152, 2818048, 3538944, 4259840, 4325376,
                                4390912, 5439488};
    int t = blockIdx.x * 256 + threadIdx.x;
    if (t >= CONV_TOT4) return;
    int j = 0;
    #pragma unroll
    for (int k = 1; k < 14; ++k) if (t >= cum[k]) j = k;
    float4 v = a.src[j][t - cum[j]];
    v.x = roundtf(v.x); v.y = roundtf(v.y); v.z = roundtf(v.z); v.w = roundtf(v.w);
    dst[t] = v;
}

// ---------------- rmsnorm (tf32-rounded output) ----------------
__global__ void rmsnorm_kernel(const float* __restrict__ x,
                               const float* __restrict__ sc,
                               float* __restrict__ out) {
    int row = blockIdx.x;
    int t = threadIdx.x;
    const float4* xr = (const float4*)(x + (size_t)row * D_);
    float4 v = xr[t];
    float ss = v.x * v.x + v.y * v.y + v.z * v.z + v.w * v.w;
    #pragma unroll
    for (int o = 16; o; o >>= 1) ss += __shfl_xor_sync(0xffffffffu, ss, o);
    __shared__ float sred[8];
    if ((t & 31) == 0) sred[t >> 5] = ss;
    __syncthreads();
    if (t < 8) {
        float s2 = sred[t];
        #pragma unroll
        for (int o = 4; o; o >>= 1) s2 += __shfl_xor_sync(0xffu, s2, o);
        if (t == 0) sred[0] = s2;
    }
    __syncthreads();
    float inv = rsqrtf(sred[0] * (1.0f / D_) + 1e-6f);
    float4 sv = ((const float4*)sc)[t];
    float4 ov = make_float4(roundtf(v.x * inv * sv.x), roundtf(v.y * inv * sv.y),
                            roundtf(v.z * inv * sv.z), roundtf(v.w * inv * sv.w));
    ((float4*)(out + (size_t)row * D_))[t] = ov;
}

// ---------------- tf32 tensor-core GEMM (GBK=32, LDSM A m-major + LDSM B n-major) ------
// Operands pre-rounded to tf32 (RNA). C = alpha*A*B (+bias)(gelu)(*mulin)
// (+residual)(+=C)(round_out). A[M,K], B[K,N] row-major. M mult 128, K mult 32.
#define GBM 128
#define GBN 128
#define GBK 32
#define PIT 36
#define TILEF (128 * PIT)                 // floats per operand tile
#define GEMM_SMEM (4 * TILEF * 4)         // 2 bufs x (A + B)

__global__ __launch_bounds__(256, 2)
void gemm_tc_kernel(const float* __restrict__ A, const float* __restrict__ Bm,
                    float* __restrict__ C, int M, int N, int K,
                    float alpha,
                    const float* __restrict__ bias,
                    const float* __restrict__ mulin,
                    const float* __restrict__ residual,
                    int do_gelu, int accumulate, int round_out, int kv_pad, int seg_rows,
                    long long sA, long long sB, long long sC,
                    long long sBias, long long sRes) {
    int z = blockIdx.z;
    A  += (size_t)z * sA;
    Bm += (size_t)z * sB;
    C  += (size_t)z * sC;
    if (bias)     bias     += (size_t)z * sBias;
    if (residual) residual += (size_t)z * sRes;

    extern __shared__ __align__(16) float sm[];
    // As(buf) = sm + buf*TILEF ; Bs(buf) = sm + 2*TILEF + buf*TILEF

    int tid  = threadIdx.x;
    int lane = tid & 31;
    int wid  = tid >> 5;
    int grpr = lane >> 2;
    int grpc = lane & 3;
    int warp_m = (wid & 1) * 64;
    int warp_n = (wid >> 1) * 32;
    int bm = blockIdx.y * GBM;
    int bn = blockIdx.x * GBN;

    // A loader: rows ar, ar+64; k chunk ac..ac+7
    int ar = tid >> 2;
    int ac = (tid & 3) * 8;
    // B loader: n-major; n = nB, k half kh..kh+15 (scalar k-strided gmem reads)
    int nB = tid & 127;
    int kh = (tid >> 7) * 16;
    int bok = (bn + nB < N);
    const float* Bp = Bm + (bok ? bn + nB : 0);

    uint32_t smB = smem_u32(sm);
    uint32_t aLane = smB + (((lane & 15) * PIT + (lane >> 4) * 4) + warp_m * PIT) * 4u;
    uint32_t bLane = smB + 2u * TILEF * 4u
                   + (((warp_n + (lane & 7) + ((lane >> 4) * 8)) * PIT
                       + ((lane >> 3) & 1) * 4)) * 4u;

    float acc[4][4][4];
    #pragma unroll
    for (int i = 0; i < 4; ++i)
        #pragma unroll
        for (int j = 0; j < 4; ++j)
            #pragma unroll
            for (int k = 0; k < 4; ++k) acc[i][j][k] = 0.0f;

    int ntiles = K / GBK;
    float4 aR[4], bR[4];

    // prefetch + store tile 0 into buf 0
    {
        const float* Ap = A + (size_t)(bm + ar) * K + ac;
        aR[0] = *(const float4*)Ap;
        aR[1] = *(const float4*)(Ap + 4);
        aR[2] = *(const float4*)(Ap + (size_t)64 * K);
        aR[3] = *(const float4*)(Ap + (size_t)64 * K + 4);
        if (bok) {
            #pragma unroll
            for (int i = 0; i < 4; ++i) {
                bR[i].x = Bp[(size_t)(kh + 4 * i + 0) * N];
                bR[i].y = Bp[(size_t)(kh + 4 * i + 1) * N];
                bR[i].z = Bp[(size_t)(kh + 4 * i + 2) * N];
                bR[i].w = Bp[(size_t)(kh + 4 * i + 3) * N];
            }
        } else {
            #pragma unroll
            for (int i = 0; i < 4; ++i) bR[i] = make_float4(0.f, 0.f, 0.f, 0.f);
        }
        float* As0 = sm;
        float* Bs0 = sm + 2 * TILEF;
        *(float4*)&As0[ar * PIT + ac]            = aR[0];
        *(float4*)&As0[ar * PIT + ac + 4]        = aR[1];
        *(float4*)&As0[(ar + 64) * PIT + ac]     = aR[2];
        *(float4*)&As0[(ar + 64) * PIT + ac + 4] = aR[3];
        #pragma unroll
        for (int i = 0; i < 4; ++i)
            *(float4*)&Bs0[nB * PIT + kh + 4 * i] = bR[i];
    }
    __syncthreads();

    for (int kt = 0; kt < ntiles; ++kt) {
        if (kt + 1 < ntiles) {
            const float* Ap = A + (size_t)(bm + ar) * K + (kt + 1) * GBK + ac;
            aR[0] = *(const float4*)Ap;
            aR[1] = *(const float4*)(Ap + 4);
            aR[2] = *(const float4*)(Ap + (size_t)64 * K);
            aR[3] = *(const float4*)(Ap + (size_t)64 * K + 4);
            if (bok) {
                const float* Bn = Bp + (size_t)(kt + 1) * GBK * N;
                #pragma unroll
                for (int i = 0; i < 4; ++i) {
                    bR[i].x = Bn[(size_t)(kh + 4 * i + 0) * N];
                    bR[i].y = Bn[(size_t)(kh + 4 * i + 1) * N];
                    bR[i].z = Bn[(size_t)(kh + 4 * i + 2) * N];
                    bR[i].w = Bn[(size_t)(kh + 4 * i + 3) * N];
                }
            }
        }
        // compute on buf (kt & 1)
        uint32_t aBuf = aLane + (uint32_t)(kt & 1) * TILEF * 4u;
        uint32_t bBuf = bLane + (uint32_t)(kt & 1) * TILEF * 4u;
        #pragma unroll
        for (int ks = 0; ks < 4; ++ks) {
            unsigned af[4][4];
            #pragma unroll
            for (int ma = 0; ma < 4; ++ma)
                ldsm4(af[ma][0], af[ma][1], af[ma][2], af[ma][3],
                      aBuf + (uint32_t)((ma * 16 * PIT + ks * 8) * 4));
            #pragma unroll
            for (int p = 0; p < 2; ++p) {
                unsigned kb[4];
                ldsm4(kb[0], kb[1], kb[2], kb[3],
                      bBuf + (uint32_t)((p * 16 * PIT + ks * 8) * 4));
                #pragma unroll
                for (int ma = 0; ma < 4; ++ma) {
                    mma8(acc[ma][2 * p + 0], af[ma], kb[0], kb[1]);
                    mma8(acc[ma][2 * p + 1], af[ma], kb[2], kb[3]);
                }
            }
        }
        if (kt + 1 < ntiles) {
            float* ad = sm + ((kt + 1) & 1) * TILEF;
            float* bd = sm + 2 * TILEF + ((kt + 1) & 1) * TILEF;
            *(float4*)&ad[ar * PIT + ac]            = aR[0];
            *(float4*)&ad[ar * PIT + ac + 4]        = aR[1];
            *(float4*)&ad[(ar + 64) * PIT + ac]     = aR[2];
            *(float4*)&ad[(ar + 64) * PIT + ac + 4] = aR[3];
            #pragma unroll
            for (int i = 0; i < 4; ++i)
                *(float4*)&bd[nB * PIT + kh + 4 * i] = bR[i];
            __syncthreads();
        }
    }

    // epilogue: element pairs at (m, n), (m, n+1)
    #pragma unroll
    for (int ma = 0; ma < 4; ++ma) {
        #pragma unroll
        for (int na = 0; na < 4; ++na) {
            int n = bn + warp_n + na * 8 + 2 * grpc;
            if (n >= N) continue;
            #pragma unroll
            for (int half = 0; half < 2; ++half) {
                int m = bm + warp_m + ma * 16 + grpr + half * 8;
                float v0 = alpha * acc[ma][na][half * 2 + 0];
                float v1 = alpha * acc[ma][na][half * 2 + 1];
                if (bias) { v0 += bias[n]; v1 += bias[n + 1]; }
                if (do_gelu) { v0 = gelu_f(v0); v1 = gelu_f(v1); }
                if (mulin) {
                    float2 mv = *(const float2*)(mulin + (size_t)m * N + n);
                    v0 *= mv.x; v1 *= mv.y;
                }
                if (residual) {
                    float2 rv = *(const float2*)(residual + (size_t)m * N + n);
                    v0 += rv.x; v1 += rv.y;
                }
                long long orow = m;
                if (kv_pad) orow = (long long)m + (long long)kv_pad * (m / seg_rows + 1);
                float* cp = C + (size_t)orow * N + n;
                if (accumulate) {
                    float2 cv = *(const float2*)cp;
                    v0 += cv.x; v1 += cv.y;
                }
                if (round_out) { v0 = roundtf(v0); v1 = roundtf(v1); }
                *(float2*)cp = make_float2(v0, v1);
            }
        }
    }
}

// ---------------- relative position bias table ----------------
__global__ void biastab_kernel(const float* __restrict__ relpos, float* __restrict__ tab) {
    int idx = blockIdx.x * 256 + threadIdx.x;
    if (idx >= H_ * L_) return;
    int h = idx / L_, rel = idx % L_;
    int bucket;
    if (rel < 16) {
        bucket = rel;
    } else {
        float lg = logf((float)rel * (1.0f / 16.0f)) * (16.0f / 2.0794415416798357f);
        bucket = 16 + (int)lg;
        if (bucket > 31) bucket = 31;
    }
    tab[idx] = relpos[h * NB_ + bucket];
}

// ---------------- prefix KV copy (tf32-rounded) ----------------
__global__ void prefix_kernel(const float* __restrict__ pk, const float* __restrict__ pv,
                              float* __restrict__ kc, float* __restrict__ vc, int sel) {
    int b = blockIdx.y;
    int i = blockIdx.x * 256 + threadIdx.x;
    if (i >= P_ * D_) return;
    size_t src = ((size_t)(b * 2 + sel)) * (P_ * D_) + i;
    size_t dst = (size_t)b * LK_ * D_ + i;
    kc[dst] = roundtf(pk[src]);
    vc[dst] = roundtf(pv[src]);
}

// ---------------- tensor-core flash attention (LDSM for Q/K/P fragments) --------------
#define ATTN_SMEM_TC ((64 * 68 + 64 * 72 + 64 * 68) * 4 + L_ * 4)

template <bool CAUSAL>
__global__ __launch_bounds__(128)
void attn_tc_kernel(const float* __restrict__ Q, const float* __restrict__ Kc,
                    const float* __restrict__ Vc, float* __restrict__ O,
                    const float* __restrict__ btab) {
    extern __shared__ __align__(16) unsigned smu[];
    unsigned* Ks = smu;                      // [64][68]
    unsigned* Vs = Ks + 64 * 68;             // [64][72]
    unsigned* Ps = Vs + 64 * 72;             // [64][68]
    float* bsh = (float*)(Ps + 64 * 68);     // [1024]

    int q0 = blockIdx.x * 64;
    int h  = blockIdx.y;
    int b  = blockIdx.z;
    int tid  = threadIdx.x;
    int w    = tid >> 5;
    int lane = tid & 31;
    int grpr = lane >> 2;
    int grpc = lane & 3;

    const float* Qb = Q  + (size_t)(b * L_)  * D_ + h * HD_;
    const float* Kb = Kc + (size_t)(b * LK_) * D_ + h * HD_;
    const float* Vb = Vc + (size_t)(b * LK_) * D_ + h * HD_;

    uint32_t ksU = smem_u32(Ks);
    uint32_t psU = smem_u32(Ps);
    uint32_t laneA = (((lane & 15) * 68 + (lane >> 4) * 4)) * 4u;
    uint32_t laneK = ((((lane & 7) + (lane >> 4) * 8) * 68 + ((lane >> 3) & 1) * 4)) * 4u;

    for (int i = tid; i < 64 * 16; i += 128) {
        int r = i >> 4, c4 = i & 15;
        float4 v = *(const float4*)(Qb + (size_t)(q0 + r) * D_ + c4 * 4);
        *(float4*)&Ks[r * 68 + c4 * 4] = v;
    }
    if (CAUSAL) {
        for (int i = tid; i < L_; i += 128) bsh[i] = btab[h * L_ + i];
    }
    __syncthreads();

    unsigned qa[8][4];
    {
        uint32_t qBase = ksU + laneA + (uint32_t)(w * 16 * 68 * 4);
        #pragma unroll
        for (int ks = 0; ks < 8; ++ks)
            ldsm4(qa[ks][0], qa[ks][1], qa[ks][2], qa[ks][3], qBase + ks * 32u);
    }

    float m0r = -1e30f, m1r = -1e30f, l0 = 0.0f, l1 = 0.0f;
    float oacc[8][4];
    #pragma unroll
    for (int na = 0; na < 8; ++na)
        #pragma unroll
        for (int k = 0; k < 4; ++k) oacc[na][k] = 0.0f;

    int r0g = q0 + w * 16 + grpr;
    int r1g = r0g + 8;

    int ntiles = (LK_ + 63) / 64;
    if (CAUSAL) {
        int need = blockIdx.x + 2;
        if (need < ntiles) ntiles = need;
    }

    for (int kt = 0; kt < ntiles; ++kt) {
        int k0 = kt * 64;
        __syncthreads();
        for (int i = tid; i < 64 * 16; i += 128) {
            int r = i >> 4, c4 = i & 15;
            int j = k0 + r;
            float4 kv, vv;
            if (j < LK_) {
                kv = *(const float4*)(Kb + (size_t)j * D_ + c4 * 4);
                vv = *(const float4*)(Vb + (size_t)j * D_ + c4 * 4);
            } else {
                kv = make_float4(0.f, 0.f, 0.f, 0.f);
                vv = kv;
            }
            *(float4*)&Ks[r * 68 + c4 * 4] = kv;
            *(float4*)&Vs[r * 72 + c4 * 4] = vv;
        }
        __syncthreads();

        float sacc[8][4];
        #pragma unroll
        for (int na = 0; na < 8; ++na)
            #pragma unroll
            for (int k = 0; k < 4; ++k) sacc[na][k] = 0.0f;
        uint32_t kBase = ksU + laneK;
        #pragma unroll
        for (int ks = 0; ks < 8; ++ks) {
            #pragma unroll
            for (int nap = 0; nap < 4; ++nap) {
                unsigned kb[4];
                ldsm4(kb[0], kb[1], kb[2], kb[3],
                      kBase + (uint32_t)((nap * 16 * 68 + ks * 8) * 4));
                mma8(sacc[2 * nap + 0], qa[ks], kb[0], kb[1]);
                mma8(sacc[2 * nap + 1], qa[ks], kb[2], kb[3]);
            }
        }

        float rm0 = -1e30f, rm1 = -1e30f;
        #pragma unroll
        for (int na = 0; na < 8; ++na) {
            int j0 = k0 + na * 8 + 2 * grpc;
            int j1 = j0 + 1;
            if (CAUSAL) {
                if (j0 >= P_) {
                    int kp = j0 - P_;
                    if (kp > r0g) sacc[na][0] = -1e30f; else sacc[na][0] += bsh[r0g - kp];
                    if (kp > r1g) sacc[na][2] = -1e30f; else sacc[na][2] += bsh[r1g - kp];
                }
                if (j1 >= P_) {
                    int kp = j1 - P_;
                    if (kp > r0g) sacc[na][1] = -1e30f; else sacc[na][1] += bsh[r0g - kp];
                    if (kp > r1g) sacc[na][3] = -1e30f; else sacc[na][3] += bsh[r1g - kp];
                }
            } else {
                if (j0 >= LK_) { sacc[na][0] = -1e30f; sacc[na][2] = -1e30f; }
                if (j1 >= LK_) { sacc[na][1] = -1e30f; sacc[na][3] = -1e30f; }
            }
            rm0 = fmaxf(rm0, fmaxf(sacc[na][0], sacc[na][1]));
            rm1 = fmaxf(rm1, fmaxf(sacc[na][2], sacc[na][3]));
        }
        rm0 = fmaxf(rm0, __shfl_xor_sync(0xffffffffu, rm0, 1));
        rm0 = fmaxf(rm0, __shfl_xor_sync(0xffffffffu, rm0, 2));
        rm1 = fmaxf(rm1, __shfl_xor_sync(0xffffffffu, rm1, 1));
        rm1 = fmaxf(rm1, __shfl_xor_sync(0xffffffffu, rm1, 2));

        float mn0 = fmaxf(m0r, rm0);
        float mn1 = fmaxf(m1r, rm1);
        float cf0 = __expf(m0r - mn0);
        float cf1 = __expf(m1r - mn1);
        l0 *= cf0; l1 *= cf1;
        m0r = mn0; m1r = mn1;
        #pragma unroll
        for (int na = 0; na < 8; ++na) {
            oacc[na][0] *= cf0; oacc[na][1] *= cf0;
            oacc[na][2] *= cf1; oacc[na][3] *= cf1;
        }

        float ps0 = 0.0f, ps1 = 0.0f;
        int pr = w * 16 + grpr;
        #pragma unroll
        for (int na = 0; na < 8; ++na) {
            float p0 = __expf(sacc[na][0] - mn0);
            float p1 = __expf(sacc[na][1] - mn0);
            float p2 = __expf(sacc[na][2] - mn1);
            float p3 = __expf(sacc[na][3] - mn1);
            ps0 += p0 + p1;
            ps1 += p2 + p3;
            uint2 u01; u01.x = f2tf(p0); u01.y = f2tf(p1);
            uint2 u23; u23.x = f2tf(p2); u23.y = f2tf(p3);
            *(uint2*)&Ps[pr * 68 + na * 8 + 2 * grpc]       = u01;
            *(uint2*)&Ps[(pr + 8) * 68 + na * 8 + 2 * grpc] = u23;
        }
        ps0 += __shfl_xor_sync(0xffffffffu, ps0, 1);
        ps0 += __shfl_xor_sync(0xffffffffu, ps0, 2);
        ps1 += __shfl_xor_sync(0xffffffffu, ps1, 1);
        ps1 += __shfl_xor_sync(0xffffffffu, ps1, 2);
        l0 += ps0; l1 += ps1;

        __syncwarp();

        uint32_t pBase = psU + laneA + (uint32_t)(w * 16 * 68 * 4);
        #pragma unroll
        for (int ks = 0; ks < 8; ++ks) {
            unsigned pa[4];
            ldsm4(pa[0], pa[1], pa[2], pa[3], pBase + ks * 32u);
            #pragma unroll
            for (int na = 0; na < 8; ++na) {
                unsigned b0 = Vs[(ks * 8 + grpc) * 72 + na * 8 + grpr];
                unsigned b1 = Vs[(ks * 8 + 4 + grpc) * 72 + na * 8 + grpr];
                mma8(oacc[na], pa, b0, b1);
            }
        }
    }

    float inv0 = 1.0f / l0;
    float inv1 = 1.0f / l1;
    float* Ob = O + (size_t)(b * L_) * D_ + h * HD_;
    int qr0 = q0 + w * 16 + grpr;
    #pragma unroll
    for (int na = 0; na < 8; ++na) {
        int d = na * 8 + 2 * grpc;
        *(float2*)(Ob + (size_t)qr0 * D_ + d) =
            make_float2(roundtf(oacc[na][0] * inv0), roundtf(oacc[na][1] * inv0));
        *(float2*)(Ob + (size_t)(qr0 + 8) * D_ + d) =
            make_float2(roundtf(oacc[na][2] * inv1), roundtf(oacc[na][3] * inv1));
    }
}

// ---------------- host side ----------------
static void gemm(const float* A, const float* Bm, float* C, int M, int N, int K,
                 float alpha, const float* bias, const float* mulin,
                 const float* residual,
                 int do_gelu, int accumulate, int round_out, int kv_pad, int seg_rows,
                 long long sA, long long sB, long long sC,
                 long long sBias, long long sRes, int batches) {
    dim3 grid((N + GBN - 1) / GBN, (M + GBM - 1) / GBM, batches);
    gemm_tc_kernel<<<grid, 256, GEMM_SMEM>>>(A, Bm, C, M, N, K, alpha, bias, mulin,
                                             residual, do_gelu, accumulate, round_out,
                                             kv_pad, seg_rows, sA, sB, sC, sBias, sRes);
}

extern "C" void kernel_launch(void* const* d_in, const int* in_sizes, int n_in,
                              void* d_out, int out_size) {
    const float* inputs  = (const float*)d_in[0];
    const float* encoded = (const float*)d_in[1];
    const float* awd     = (const float*)d_in[2];
    const float* awu     = (const float*)d_in[3];
    const float* abd     = (const float*)d_in[4];
    const float* abu     = (const float*)d_in[5];
    const float* pk      = (const float*)d_in[6];
    const float* pv      = (const float*)d_in[7];
    const float* ln1     = (const float*)d_in[8];
    const float* ln2     = (const float*)d_in[9];
    const float* ln3     = (const float*)d_in[10];
    const float* sa_wq   = (const float*)d_in[11];
    const float* sa_wk   = (const float*)d_in[12];
    const float* sa_wv   = (const float*)d_in[13];
    const float* sa_wo   = (const float*)d_in[14];
    const float* ca_wq   = (const float*)d_in[15];
    const float* ca_wk   = (const float*)d_in[16];
    const float* ca_wv   = (const float*)d_in[17];
    const float* ca_wo   = (const float*)d_in[18];
    const float* relpos  = (const float*)d_in[19];
    const float* wi0     = (const float*)d_in[20];
    const float* wi1     = (const float*)d_in[21];
    const float* wo      = (const float*)d_in[22];
    float* out = (float*)d_out;

    float *xn, *q, *kc, *vc, *o, *x, *y, *h0, *h1, *az, *bt, *wtf;
    cudaGetSymbolAddress((void**)&xn, g_xn);
    cudaGetSymbolAddress((void**)&q,  g_q);
    cudaGetSymbolAddress((void**)&kc, g_kc);
    cudaGetSymbolAddress((void**)&vc, g_vc);
    cudaGetSymbolAddress((void**)&o,  g_o);
    cudaGetSymbolAddress((void**)&x,  g_x);
    cudaGetSymbolAddress((void**)&y,  g_y);
    cudaGetSymbolAddress((void**)&h0, g_h0);
    cudaGetSymbolAddress((void**)&h1, g_h1);
    cudaGetSymbolAddress((void**)&az, g_az);
    cudaGetSymbolAddress((void**)&bt, g_bt);
    cudaGetSymbolAddress((void**)&wtf, g_wtf);

    cudaFuncSetAttribute(gemm_tc_kernel, cudaFuncAttributeMaxDynamicSharedMemorySize, GEMM_SMEM);
    cudaFuncSetAttribute(attn_tc_kernel<true>,  cudaFuncAttributeMaxDynamicSharedMemorySize, ATTN_SMEM_TC);
    cudaFuncSetAttribute(attn_tc_kernel<false>, cudaFuncAttributeMaxDynamicSharedMemorySize, ATTN_SMEM_TC);

    // ---- convert weights + encoded to tf32 (one pass) ----
    ConvArgs ca;
    ca.src[0]  = (const float4*)sa_wq;  ca.src[1]  = (const float4*)sa_wk;
    ca.src[2]  = (const float4*)sa_wv;  ca.src[3]  = (const float4*)sa_wo;
    ca.src[4]  = (const float4*)ca_wq;  ca.src[5]  = (const float4*)ca_wk;
    ca.src[6]  = (const float4*)ca_wv;  ca.src[7]  = (const float4*)ca_wo;
    ca.src[8]  = (const float4*)wi0;    ca.src[9]  = (const float4*)wi1;
    ca.src[10] = (const float4*)wo;     ca.src[11] = (const float4*)awd;
    ca.src[12] = (const float4*)awu;    ca.src[13] = (const float4*)encoded;
    conv_kernel<<<(CONV_TOT4 + 255) / 256, 256>>>(ca, (float4*)wtf);

    const float qscale = 0.125f;   // HD^-0.5
    const float* enc_tf = wtf + ENCo;

    // ---- self attention ----
    rmsnorm_kernel<<<M_, 256>>>(inputs, ln1, xn);
    gemm(xn, wtf + WQ0o, q,  M_, D_, D_, qscale, 0, 0, 0, 0, 0, 1, 0, 0,  0, 0, 0, 0, 0, 1);
    gemm(xn, wtf + WK0o, kc, M_, D_, D_, 1.0f,   0, 0, 0, 0, 0, 1, P_, L_, 0, 0, 0, 0, 0, 1);
    gemm(xn, wtf + WV0o, vc, M_, D_, D_, 1.0f,   0, 0, 0, 0, 0, 1, P_, L_, 0, 0, 0, 0, 0, 1);
    prefix_kernel<<<dim3((P_ * D_ + 255) / 256, B_), 256>>>(pk, pv, kc, vc, 0);
    biastab_kernel<<<(H_ * L_ + 255) / 256, 256>>>(relpos, bt);
    attn_tc_kernel<true><<<dim3(L_ / 64, H_, B_), 128, ATTN_SMEM_TC>>>(q, kc, vc, o, bt);
    gemm(o, wtf + WO0o, x, M_, D_, D_, 1.0f, 0, 0, inputs, 0, 0, 0, 0, 0, 0, 0, 0, 0, 0, 1);

    // ---- cross attention ----
    rmsnorm_kernel<<<M_, 256>>>(x, ln2, xn);
    gemm(xn,     wtf + WQ1o, q,  M_, D_, D_, qscale, 0, 0, 0, 0, 0, 1, 0, 0,  0, 0, 0, 0, 0, 1);
    gemm(enc_tf, wtf + WK1o, kc, M_, D_, D_, 1.0f,   0, 0, 0, 0, 0, 1, P_, L_, 0, 0, 0, 0, 0, 1);
    gemm(enc_tf, wtf + WV1o, vc, M_, D_, D_, 1.0f,   0, 0, 0, 0, 0, 1, P_, L_, 0, 0, 0, 0, 0, 1);
    prefix_kernel<<<dim3((P_ * D_ + 255) / 256, B_), 256>>>(pk, pv, kc, vc, 1);
    attn_tc_kernel<false><<<dim3(L_ / 64, H_, B_), 128, ATTN_SMEM_TC>>>(q, kc, vc, o, 0);
    gemm(o, wtf + WO1o, y, M_, D_, D_, 1.0f, 0, 0, x, 0, 0, 0, 0, 0, 0, 0, 0, 0, 0, 1);

    // ---- MLP + adapter (gate fused into wi1 epilogue) ----
    rmsnorm_kernel<<<M_, 256>>>(y, ln3, xn);   // xn = lz (tf32-rounded)
    gemm(xn, wtf + WI0o, h0, M_, F_, D_, 1.0f, 0, 0, 0, 1, 0, 0, 0, 0, 0, 0, 0, 0, 0, 1);  // h0 = gelu(lz@wi0)
    gemm(xn, wtf + WI1o, h1, M_, F_, D_, 1.0f, 0, h0, 0, 0, 0, 1, 0, 0, 0, 0, 0, 0, 0, 1); // h1 = (lz@wi1)*h0 (rounded)
    gemm(h1, wtf + WOMo, out, M_, D_, F_, 1.0f, 0, 0, y, 0, 0, 0, 0, 0, 0, 0, 0, 0, 0, 1);

    // adapter: az = gelu(lz @ wd + bd) (rounded);  out += az @ wu + bu
    gemm(xn, wtf + AWDo, az, L_, A_, D_, 1.0f, abd, 0, 0, 1, 0, 1, 0, 0,
         (long long)L_ * D_, (long long)D_ * A_, (long long)L_ * A_, A_, 0, B_);
    gemm(az, wtf + AWUo, out, L_, D_, A_, 1.0f, abu, 0, 0, 0, 1, 0, 0, 0,
         (long long)L_ * A_, (long long)A_ * D_, (long long)L_ * D_, D_, 0, B_);
}

// round 14
// speedup vs baseline: 1.0685x; 1.0309x over previous
#include <cuda_runtime.h>
#include <math.h>
#include <stdint.h>

#define D_  1024
#define H_  16
#define HD_ 64
#define F_  2816
#define A_  64
#define P_  30
#define NB_ 32
#define B_  4
#define L_  1024
#define LK_ 1054            // P_ + L_
#define M_  4096            // B_ * L_

// ---------------- scratch (device globals; no runtime allocation) ----------------
__device__ float g_xn[M_ * D_];
__device__ float g_q [M_ * D_];
__device__ float g_kc[B_ * LK_ * D_];
__device__ float g_vc[B_ * LK_ * D_];
__device__ float g_o [M_ * D_];
__device__ float g_x [M_ * D_];
__device__ float g_y [M_ * D_];
__device__ float g_h0[(size_t)M_ * F_];
__device__ float g_h1[(size_t)M_ * F_];
__device__ float g_az[B_ * L_ * A_];
__device__ float g_bt[H_ * L_];
__device__ float g_wtf[21757952];      // tf32-rounded weights + encoded

// float offsets into g_wtf
#define WQ0o  0
#define WK0o  1048576
#define WV0o  2097152
#define WO0o  3145728
#define WQ1o  4194304
#define WK1o  5242880
#define WV1o  6291456
#define WO1o  7340032
#define WI0o  8388608        // packed gated-MLP weights [K, 5632]
#define WOMo  14155776
#define AWDo  17039360
#define AWUo  17301504
#define ENCo  17563648

// ---------------- helpers ----------------
__device__ __forceinline__ float gelu_f(float x) {
    const float c = 0.7978845608028654f;       // sqrt(2/pi)
    float t = tanhf(c * (x + 0.044715f * x * x * x));
    return 0.5f * x * (1.0f + t);
}

__device__ __forceinline__ unsigned f2tf(float f) {
    unsigned u;
    asm("cvt.rna.tf32.f32 %0, %1;" : "=r"(u) : "f"(f));
    return u;
}
__device__ __forceinline__ float roundtf(float f) { return __uint_as_float(f2tf(f)); }

__device__ __forceinline__ void mma8(float* c, const unsigned* a, unsigned b0, unsigned b1) {
    asm volatile(
        "mma.sync.aligned.m16n8k8.row.col.f32.tf32.tf32.f32 "
        "{%0,%1,%2,%3},{%4,%5,%6,%7},{%8,%9},{%0,%1,%2,%3};"
        : "+f"(c[0]), "+f"(c[1]), "+f"(c[2]), "+f"(c[3])
        : "r"(a[0]), "r"(a[1]), "r"(a[2]), "r"(a[3]), "r"(b0), "r"(b1));
}

__device__ __forceinline__ void ldsm4(unsigned& r0, unsigned& r1, unsigned& r2, unsigned& r3,
                                      uint32_t addr) {
    asm volatile("ldmatrix.sync.aligned.m8n8.x4.shared.b16 {%0,%1,%2,%3}, [%4];"
                 : "=r"(r0), "=r"(r1), "=r"(r2), "=r"(r3) : "r"(addr));
}

__device__ __forceinline__ uint32_t smem_u32(const void* p) {
    uint32_t a;
    asm("{ .reg .u64 t; cvta.to.shared.u64 t, %1; cvt.u32.u64 %0, t; }" : "=r"(a) : "l"(p));
    return a;
}

// ---------------- weight/encoded tf32 conversion (12 flat sources) ----------------
struct ConvArgs { const float4* src[12]; };
#define CONV_TOT4 3997696

__global__ void conv_kernel(ConvArgs a, float* __restrict__ wtf) {
    static const int cum[13] = {0, 262144, 524288, 786432, 1048576, 1310720, 1572864,
                                1835008, 2097152, 2818048, 2883584, 2949120, 3997696};
    static const int dstoff4[12] = {WQ0o / 4, WK0o / 4, WV0o / 4, WO0o / 4,
                                    WQ1o / 4, WK1o / 4, WV1o / 4, WO1o / 4,
                                    WOMo / 4, AWDo / 4, AWUo / 4, ENCo / 4};
    int t = blockIdx.x * 256 + threadIdx.x;
    if (t >= CONV_TOT4) return;
    int j = 0;
    #pragma unroll
    for (int k = 1; k < 12; ++k) if (t >= cum[k]) j = k;
    float4 v = a.src[j][t - cum[j]];
    v.x = roundtf(v.x); v.y = roundtf(v.y); v.z = roundtf(v.z); v.w = roundtf(v.w);
    ((float4*)wtf)[dstoff4[j] + (t - cum[j])] = v;
}

// ---------------- wi0/wi1 interleave + round: packed[k][16t + s] ----------------
__global__ void ilv_kernel(const float* __restrict__ w0, const float* __restrict__ w1,
                           float* __restrict__ dst) {
    int i = blockIdx.x * 256 + threadIdx.x;
    if (i >= D_ * F_) return;
    int k = i / F_, j = i % F_;
    size_t base = (size_t)k * (2 * F_) + ((j >> 3) << 4) + (j & 7);
    dst[base]     = roundtf(w0[i]);
    dst[base + 8] = roundtf(w1[i]);
}

// ---------------- rmsnorm (tf32-rounded output) ----------------
__global__ void rmsnorm_kernel(const float* __restrict__ x,
                               const float* __restrict__ sc,
                               float* __restrict__ out) {
    int row = blockIdx.x;
    int t = threadIdx.x;
    const float4* xr = (const float4*)(x + (size_t)row * D_);
    float4 v = xr[t];
    float ss = v.x * v.x + v.y * v.y + v.z * v.z + v.w * v.w;
    #pragma unroll
    for (int o = 16; o; o >>= 1) ss += __shfl_xor_sync(0xffffffffu, ss, o);
    __shared__ float sred[8];
    if ((t & 31) == 0) sred[t >> 5] = ss;
    __syncthreads();
    if (t < 8) {
        float s2 = sred[t];
        #pragma unroll
        for (int o = 4; o; o >>= 1) s2 += __shfl_xor_sync(0xffu, s2, o);
        if (t == 0) sred[0] = s2;
    }
    __syncthreads();
    float inv = rsqrtf(sred[0] * (1.0f / D_) + 1e-6f);
    float4 sv = ((const float4*)sc)[t];
    float4 ov = make_float4(roundtf(v.x * inv * sv.x), roundtf(v.y * inv * sv.y),
                            roundtf(v.z * inv * sv.z), roundtf(v.w * inv * sv.w));
    ((float4*)(out + (size_t)row * D_))[t] = ov;
}

// ---------------- tf32 tensor-core GEMM (GBK=32, LDSM A m-major + LDSM B n-major) ------
// Operands pre-rounded to tf32 (RNA). Normal mode: C = alpha*A*B (+bias)(gelu)(*mulin)
// (+residual)(+=C)(round_out). gate_pack mode: B packed (wi0|wi1 8-col interleave),
// C[m][n] = roundtf( acc_wi1 * roundtf(gelu(acc_wi0)) ), C width = N/2.
#define GBM 128
#define GBN 128
#define GBK 32
#define PIT 36
#define TILEF (128 * PIT)
#define GEMM_SMEM (4 * TILEF * 4)

__global__ __launch_bounds__(256, 2)
void gemm_tc_kernel(const float* __restrict__ A, const float* __restrict__ Bm,
                    float* __restrict__ C, int M, int N, int K,
                    float alpha,
                    const float* __restrict__ bias,
                    const float* __restrict__ mulin,
                    const float* __restrict__ residual,
                    int do_gelu, int accumulate, int round_out, int gate_pack,
                    int kv_pad, int seg_rows,
                    long long sA, long long sB, long long sC,
                    long long sBias, long long sRes) {
    int z = blockIdx.z;
    A  += (size_t)z * sA;
    Bm += (size_t)z * sB;
    C  += (size_t)z * sC;
    if (bias)     bias     += (size_t)z * sBias;
    if (residual) residual += (size_t)z * sRes;

    extern __shared__ __align__(16) float sm[];

    int tid  = threadIdx.x;
    int lane = tid & 31;
    int wid  = tid >> 5;
    int grpr = lane >> 2;
    int grpc = lane & 3;
    int warp_m = (wid & 1) * 64;
    int warp_n = (wid >> 1) * 32;
    int bm = blockIdx.y * GBM;
    int bn = blockIdx.x * GBN;

    int ar = tid >> 2;
    int ac = (tid & 3) * 8;
    int nB = tid & 127;
    int kh = (tid >> 7) * 16;
    int bok = (bn + nB < N);
    const float* Bp = Bm + (bok ? bn + nB : 0);

    uint32_t smB = smem_u32(sm);
    uint32_t aLane = smB + (((lane & 15) * PIT + (lane >> 4) * 4) + warp_m * PIT) * 4u;
    uint32_t bLane = smB + 2u * TILEF * 4u
                   + (((warp_n + (lane & 7) + ((lane >> 4) * 8)) * PIT
                       + ((lane >> 3) & 1) * 4)) * 4u;

    float acc[4][4][4];
    #pragma unroll
    for (int i = 0; i < 4; ++i)
        #pragma unroll
        for (int j = 0; j < 4; ++j)
            #pragma unroll
            for (int k = 0; k < 4; ++k) acc[i][j][k] = 0.0f;

    int ntiles = K / GBK;
    float4 aR[4], bR[4];

    {
        const float* Ap = A + (size_t)(bm + ar) * K + ac;
        aR[0] = *(const float4*)Ap;
        aR[1] = *(const float4*)(Ap + 4);
        aR[2] = *(const float4*)(Ap + (size_t)64 * K);
        aR[3] = *(const float4*)(Ap + (size_t)64 * K + 4);
        if (bok) {
            #pragma unroll
            for (int i = 0; i < 4; ++i) {
                bR[i].x = Bp[(size_t)(kh + 4 * i + 0) * N];
                bR[i].y = Bp[(size_t)(kh + 4 * i + 1) * N];
                bR[i].z = Bp[(size_t)(kh + 4 * i + 2) * N];
                bR[i].w = Bp[(size_t)(kh + 4 * i + 3) * N];
            }
        } else {
            #pragma unroll
            for (int i = 0; i < 4; ++i) bR[i] = make_float4(0.f, 0.f, 0.f, 0.f);
        }
        float* As0 = sm;
        float* Bs0 = sm + 2 * TILEF;
        *(float4*)&As0[ar * PIT + ac]            = aR[0];
        *(float4*)&As0[ar * PIT + ac + 4]        = aR[1];
        *(float4*)&As0[(ar + 64) * PIT + ac]     = aR[2];
        *(float4*)&As0[(ar + 64) * PIT + ac + 4] = aR[3];
        #pragma unroll
        for (int i = 0; i < 4; ++i)
            *(float4*)&Bs0[nB * PIT + kh + 4 * i] = bR[i];
    }
    __syncthreads();

    for (int kt = 0; kt < ntiles; ++kt) {
        if (kt + 1 < ntiles) {
            const float* Ap = A + (size_t)(bm + ar) * K + (kt + 1) * GBK + ac;
            aR[0] = *(const float4*)Ap;
            aR[1] = *(const float4*)(Ap + 4);
            aR[2] = *(const float4*)(Ap + (size_t)64 * K);
            aR[3] = *(const float4*)(Ap + (size_t)64 * K + 4);
            if (bok) {
                const float* Bn = Bp + (size_t)(kt + 1) * GBK * N;
                #pragma unroll
                for (int i = 0; i < 4; ++i) {
                    bR[i].x = Bn[(size_t)(kh + 4 * i + 0) * N];
                    bR[i].y = Bn[(size_t)(kh + 4 * i + 1) * N];
                    bR[i].z = Bn[(size_t)(kh + 4 * i + 2) * N];
                    bR[i].w = Bn[(size_t)(kh + 4 * i + 3) * N];
                }
            }
        }
        uint32_t aBuf = aLane + (uint32_t)(kt & 1) * TILEF * 4u;
        uint32_t bBuf = bLane + (uint32_t)(kt & 1) * TILEF * 4u;
        #pragma unroll
        for (int ks = 0; ks < 4; ++ks) {
            unsigned af[4][4];
            #pragma unroll
            for (int ma = 0; ma < 4; ++ma)
                ldsm4(af[ma][0], af[ma][1], af[ma][2], af[ma][3],
                      aBuf + (uint32_t)((ma * 16 * PIT + ks * 8) * 4));
            #pragma unroll
            for (int p = 0; p < 2; ++p) {
                unsigned kb[4];
                ldsm4(kb[0], kb[1], kb[2], kb[3],
                      bBuf + (uint32_t)((p * 16 * PIT + ks * 8) * 4));
                #pragma unroll
                for (int ma = 0; ma < 4; ++ma) {
                    mma8(acc[ma][2 * p + 0], af[ma], kb[0], kb[1]);
                    mma8(acc[ma][2 * p + 1], af[ma], kb[2], kb[3]);
                }
            }
        }
        if (kt + 1 < ntiles) {
            float* ad = sm + ((kt + 1) & 1) * TILEF;
            float* bd = sm + 2 * TILEF + ((kt + 1) & 1) * TILEF;
            *(float4*)&ad[ar * PIT + ac]            = aR[0];
            *(float4*)&ad[ar * PIT + ac + 4]        = aR[1];
            *(float4*)&ad[(ar + 64) * PIT + ac]     = aR[2];
            *(float4*)&ad[(ar + 64) * PIT + ac + 4] = aR[3];
            #pragma unroll
            for (int i = 0; i < 4; ++i)
                *(float4*)&bd[nB * PIT + kh + 4 * i] = bR[i];
            __syncthreads();
        }
    }

    if (gate_pack) {
        // packed cols: na even = wi0, na odd = wi1, same output cols.
        int Nout = N >> 1;
        #pragma unroll
        for (int ma = 0; ma < 4; ++ma) {
            #pragma unroll
            for (int p = 0; p < 2; ++p) {
                int outn = ((bn + warp_n) >> 1) + p * 8 + 2 * grpc;
                #pragma unroll
                for (int half = 0; half < 2; ++half) {
                    int m = bm + warp_m + ma * 16 + grpr + half * 8;
                    float g0 = roundtf(gelu_f(acc[ma][2 * p][half * 2 + 0]));
                    float g1 = roundtf(gelu_f(acc[ma][2 * p][half * 2 + 1]));
                    float v0 = roundtf(acc[ma][2 * p + 1][half * 2 + 0] * g0);
                    float v1 = roundtf(acc[ma][2 * p + 1][half * 2 + 1] * g1);
                    *(float2*)(C + (size_t)m * Nout + outn) = make_float2(v0, v1);
                }
            }
        }
        return;
    }

    #pragma unroll
    for (int ma = 0; ma < 4; ++ma) {
        #pragma unroll
        for (int na = 0; na < 4; ++na) {
            int n = bn + warp_n + na * 8 + 2 * grpc;
            if (n >= N) continue;
            #pragma unroll
            for (int half = 0; half < 2; ++half) {
                int m = bm + warp_m + ma * 16 + grpr + half * 8;
                float v0 = alpha * acc[ma][na][half * 2 + 0];
                float v1 = alpha * acc[ma][na][half * 2 + 1];
                if (bias) { v0 += bias[n]; v1 += bias[n + 1]; }
                if (do_gelu) { v0 = gelu_f(v0); v1 = gelu_f(v1); }
                if (mulin) {
                    float2 mv = *(const float2*)(mulin + (size_t)m * N + n);
                    v0 *= mv.x; v1 *= mv.y;
                }
                if (residual) {
                    float2 rv = *(const float2*)(residual + (size_t)m * N + n);
                    v0 += rv.x; v1 += rv.y;
                }
                long long orow = m;
                if (kv_pad) orow = (long long)m + (long long)kv_pad * (m / seg_rows + 1);
                float* cp = C + (size_t)orow * N + n;
                if (accumulate) {
                    float2 cv = *(const float2*)cp;
                    v0 += cv.x; v1 += cv.y;
                }
                if (round_out) { v0 = roundtf(v0); v1 = roundtf(v1); }
                *(float2*)cp = make_float2(v0, v1);
            }
        }
    }
}

// ---------------- relative position bias table ----------------
__global__ void biastab_kernel(const float* __restrict__ relpos, float* __restrict__ tab) {
    int idx = blockIdx.x * 256 + threadIdx.x;
    if (idx >= H_ * L_) return;
    int h = idx / L_, rel = idx % L_;
    int bucket;
    if (rel < 16) {
        bucket = rel;
    } else {
        float lg = logf((float)rel * (1.0f / 16.0f)) * (16.0f / 2.0794415416798357f);
        bucket = 16 + (int)lg;
        if (bucket > 31) bucket = 31;
    }
    tab[idx] = relpos[h * NB_ + bucket];
}

// ---------------- prefix KV copy (tf32-rounded) ----------------
__global__ void prefix_kernel(const float* __restrict__ pk, const float* __restrict__ pv,
                              float* __restrict__ kc, float* __restrict__ vc, int sel) {
    int b = blockIdx.y;
    int i = blockIdx.x * 256 + threadIdx.x;
    if (i >= P_ * D_) return;
    size_t src = ((size_t)(b * 2 + sel)) * (P_ * D_) + i;
    size_t dst = (size_t)b * LK_ * D_ + i;
    kc[dst] = roundtf(pk[src]);
    vc[dst] = roundtf(pv[src]);
}

// ---------------- tensor-core flash attention (LDSM for Q/K/P fragments) --------------
#define ATTN_SMEM_TC ((64 * 68 + 64 * 72 + 64 * 68) * 4 + L_ * 4)

template <bool CAUSAL>
__global__ __launch_bounds__(128)
void attn_tc_kernel(const float* __restrict__ Q, const float* __restrict__ Kc,
                    const float* __restrict__ Vc, float* __restrict__ O,
                    const float* __restrict__ btab) {
    extern __shared__ __align__(16) unsigned smu[];
    unsigned* Ks = smu;                      // [64][68]
    unsigned* Vs = Ks + 64 * 68;             // [64][72]
    unsigned* Ps = Vs + 64 * 72;             // [64][68]
    float* bsh = (float*)(Ps + 64 * 68);     // [1024]

    int q0 = blockIdx.x * 64;
    int h  = blockIdx.y;
    int b  = blockIdx.z;
    int tid  = threadIdx.x;
    int w    = tid >> 5;
    int lane = tid & 31;
    int grpr = lane >> 2;
    int grpc = lane & 3;

    const float* Qb = Q  + (size_t)(b * L_)  * D_ + h * HD_;
    const float* Kb = Kc + (size_t)(b * LK_) * D_ + h * HD_;
    const float* Vb = Vc + (size_t)(b * LK_) * D_ + h * HD_;

    uint32_t ksU = smem_u32(Ks);
    uint32_t psU = smem_u32(Ps);
    uint32_t laneA = (((lane & 15) * 68 + (lane >> 4) * 4)) * 4u;
    uint32_t laneK = ((((lane & 7) + (lane >> 4) * 8) * 68 + ((lane >> 3) & 1) * 4)) * 4u;

    for (int i = tid; i < 64 * 16; i += 128) {
        int r = i >> 4, c4 = i & 15;
        float4 v = *(const float4*)(Qb + (size_t)(q0 + r) * D_ + c4 * 4);
        *(float4*)&Ks[r * 68 + c4 * 4] = v;
    }
    if (CAUSAL) {
        for (int i = tid; i < L_; i += 128) bsh[i] = btab[h * L_ + i];
    }
    __syncthreads();

    unsigned qa[8][4];
    {
        uint32_t qBase = ksU + laneA + (uint32_t)(w * 16 * 68 * 4);
        #pragma unroll
        for (int ks = 0; ks < 8; ++ks)
            ldsm4(qa[ks][0], qa[ks][1], qa[ks][2], qa[ks][3], qBase + ks * 32u);
    }

    float m0r = -1e30f, m1r = -1e30f, l0 = 0.0f, l1 = 0.0f;
    float oacc[8][4];
    #pragma unroll
    for (int na = 0; na < 8; ++na)
        #pragma unroll
        for (int k = 0; k < 4; ++k) oacc[na][k] = 0.0f;

    int r0g = q0 + w * 16 + grpr;
    int r1g = r0g + 8;

    int ntiles = (LK_ + 63) / 64;
    if (CAUSAL) {
        int need = blockIdx.x + 2;
        if (need < ntiles) ntiles = need;
    }

    for (int kt = 0; kt < ntiles; ++kt) {
        int k0 = kt * 64;
        __syncthreads();
        for (int i = tid; i < 64 * 16; i += 128) {
            int r = i >> 4, c4 = i & 15;
            int j = k0 + r;
            float4 kv, vv;
            if (j < LK_) {
                kv = *(const float4*)(Kb + (size_t)j * D_ + c4 * 4);
                vv = *(const float4*)(Vb + (size_t)j * D_ + c4 * 4);
            } else {
                kv = make_float4(0.f, 0.f, 0.f, 0.f);
                vv = kv;
            }
            *(float4*)&Ks[r * 68 + c4 * 4] = kv;
            *(float4*)&Vs[r * 72 + c4 * 4] = vv;
        }
        __syncthreads();

        float sacc[8][4];
        #pragma unroll
        for (int na = 0; na < 8; ++na)
            #pragma unroll
            for (int k = 0; k < 4; ++k) sacc[na][k] = 0.0f;
        uint32_t kBase = ksU + laneK;
        #pragma unroll
        for (int ks = 0; ks < 8; ++ks) {
            #pragma unroll
            for (int nap = 0; nap < 4; ++nap) {
                unsigned kb[4];
                ldsm4(kb[0], kb[1], kb[2], kb[3],
                      kBase + (uint32_t)((nap * 16 * 68 + ks * 8) * 4));
                mma8(sacc[2 * nap + 0], qa[ks], kb[0], kb[1]);
                mma8(sacc[2 * nap + 1], qa[ks], kb[2], kb[3]);
            }
        }

        float rm0 = -1e30f, rm1 = -1e30f;
        #pragma unroll
        for (int na = 0; na < 8; ++na) {
            int j0 = k0 + na * 8 + 2 * grpc;
            int j1 = j0 + 1;
            if (CAUSAL) {
                if (j0 >= P_) {
                    int kp = j0 - P_;
                    if (kp > r0g) sacc[na][0] = -1e30f; else sacc[na][0] += bsh[r0g - kp];
                    if (kp > r1g) sacc[na][2] = -1e30f; else sacc[na][2] += bsh[r1g - kp];
                }
                if (j1 >= P_) {
                    int kp = j1 - P_;
                    if (kp > r0g) sacc[na][1] = -1e30f; else sacc[na][1] += bsh[r0g - kp];
                    if (kp > r1g) sacc[na][3] = -1e30f; else sacc[na][3] += bsh[r1g - kp];
                }
            } else {
                if (j0 >= LK_) { sacc[na][0] = -1e30f; sacc[na][2] = -1e30f; }
                if (j1 >= LK_) { sacc[na][1] = -1e30f; sacc[na][3] = -1e30f; }
            }
            rm0 = fmaxf(rm0, fmaxf(sacc[na][0], sacc[na][1]));
            rm1 = fmaxf(rm1, fmaxf(sacc[na][2], sacc[na][3]));
        }
        rm0 = fmaxf(rm0, __shfl_xor_sync(0xffffffffu, rm0, 1));
        rm0 = fmaxf(rm0, __shfl_xor_sync(0xffffffffu, rm0, 2));
        rm1 = fmaxf(rm1, __shfl_xor_sync(0xffffffffu, rm1, 1));
        rm1 = fmaxf(rm1, __shfl_xor_sync(0xffffffffu, rm1, 2));

        float mn0 = fmaxf(m0r, rm0);
        float mn1 = fmaxf(m1r, rm1);
        float cf0 = __expf(m0r - mn0);
        float cf1 = __expf(m1r - mn1);
        l0 *= cf0; l1 *= cf1;
        m0r = mn0; m1r = mn1;
        #pragma unroll
        for (int na = 0; na < 8; ++na) {
            oacc[na][0] *= cf0; oacc[na][1] *= cf0;
            oacc[na][2] *= cf1; oacc[na][3] *= cf1;
        }

        float ps0 = 0.0f, ps1 = 0.0f;
        int pr = w * 16 + grpr;
        #pragma unroll
        for (int na = 0; na < 8; ++na) {
            float p0 = __expf(sacc[na][0] - mn0);
            float p1 = __expf(sacc[na][1] - mn0);
            float p2 = __expf(sacc[na][2] - mn1);
            float p3 = __expf(sacc[na][3] - mn1);
            ps0 += p0 + p1;
            ps1 += p2 + p3;
            uint2 u01; u01.x = f2tf(p0); u01.y = f2tf(p1);
            uint2 u23; u23.x = f2tf(p2); u23.y = f2tf(p3);
            *(uint2*)&Ps[pr * 68 + na * 8 + 2 * grpc]       = u01;
            *(uint2*)&Ps[(pr + 8) * 68 + na * 8 + 2 * grpc] = u23;
        }
        ps0 += __shfl_xor_sync(0xffffffffu, ps0, 1);
        ps0 += __shfl_xor_sync(0xffffffffu, ps0, 2);
        ps1 += __shfl_xor_sync(0xffffffffu, ps1, 1);
        ps1 += __shfl_xor_sync(0xffffffffu, ps1, 2);
        l0 += ps0; l1 += ps1;

        __syncwarp();

        uint32_t pBase = psU + laneA + (uint32_t)(w * 16 * 68 * 4);
        #pragma unroll
        for (int ks = 0; ks < 8; ++ks) {
            unsigned pa[4];
            ldsm4(pa[0], pa[1], pa[2], pa[3], pBase + ks * 32u);
            #pragma unroll
            for (int na = 0; na < 8; ++na) {
                unsigned b0 = Vs[(ks * 8 + grpc) * 72 + na * 8 + grpr];
                unsigned b1 = Vs[(ks * 8 + 4 + grpc) * 72 + na * 8 + grpr];
                mma8(oacc[na], pa, b0, b1);
            }
        }
    }

    float inv0 = 1.0f / l0;
    float inv1 = 1.0f / l1;
    float* Ob = O + (size_t)(b * L_) * D_ + h * HD_;
    int qr0 = q0 + w * 16 + grpr;
    #pragma unroll
    for (int na = 0; na < 8; ++na) {
        int d = na * 8 + 2 * grpc;
        *(float2*)(Ob + (size_t)qr0 * D_ + d) =
            make_float2(roundtf(oacc[na][0] * inv0), roundtf(oacc[na][1] * inv0));
        *(float2*)(Ob + (size_t)(qr0 + 8) * D_ + d) =
            make_float2(roundtf(oacc[na][2] * inv1), roundtf(oacc[na][3] * inv1));
    }
}

// ---------------- host side ----------------
static void gemm(const float* A, const float* Bm, float* C, int M, int N, int K,
                 float alpha, const float* bias, const float* mulin,
                 const float* residual,
                 int do_gelu, int accumulate, int round_out, int gate_pack,
                 int kv_pad, int seg_rows,
                 long long sA, long long sB, long long sC,
                 long long sBias, long long sRes, int batches) {
    dim3 grid((N + GBN - 1) / GBN, (M + GBM - 1) / GBM, batches);
    gemm_tc_kernel<<<grid, 256, GEMM_SMEM>>>(A, Bm, C, M, N, K, alpha, bias, mulin,
                                             residual, do_gelu, accumulate, round_out,
                                             gate_pack, kv_pad, seg_rows,
                                             sA, sB, sC, sBias, sRes);
}

extern "C" void kernel_launch(void* const* d_in, const int* in_sizes, int n_in,
                              void* d_out, int out_size) {
    const float* inputs  = (const float*)d_in[0];
    const float* encoded = (const float*)d_in[1];
    const float* awd     = (const float*)d_in[2];
    const float* awu     = (const float*)d_in[3];
    const float* abd     = (const float*)d_in[4];
    const float* abu     = (const float*)d_in[5];
    const float* pk      = (const float*)d_in[6];
    const float* pv      = (const float*)d_in[7];
    const float* ln1     = (const float*)d_in[8];
    const float* ln2     = (const float*)d_in[9];
    const float* ln3     = (const float*)d_in[10];
    const float* sa_wq   = (const float*)d_in[11];
    const float* sa_wk   = (const float*)d_in[12];
    const float* sa_wv   = (const float*)d_in[13];
    const float* sa_wo   = (const float*)d_in[14];
    const float* ca_wq   = (const float*)d_in[15];
    const float* ca_wk   = (const float*)d_in[16];
    const float* ca_wv   = (const float*)d_in[17];
    const float* ca_wo   = (const float*)d_in[18];
    const float* relpos  = (const float*)d_in[19];
    const float* wi0     = (const float*)d_in[20];
    const float* wi1     = (const float*)d_in[21];
    const float* wo      = (const float*)d_in[22];
    float* out = (float*)d_out;

    float *xn, *q, *kc, *vc, *o, *x, *y, *h1, *az, *bt, *wtf;
    cudaGetSymbolAddress((void**)&xn, g_xn);
    cudaGetSymbolAddress((void**)&q,  g_q);
    cudaGetSymbolAddress((void**)&kc, g_kc);
    cudaGetSymbolAddress((void**)&vc, g_vc);
    cudaGetSymbolAddress((void**)&o,  g_o);
    cudaGetSymbolAddress((void**)&x,  g_x);
    cudaGetSymbolAddress((void**)&y,  g_y);
    cudaGetSymbolAddress((void**)&h1, g_h1);
    cudaGetSymbolAddress((void**)&az, g_az);
    cudaGetSymbolAddress((void**)&bt, g_bt);
    cudaGetSymbolAddress((void**)&wtf, g_wtf);

    cudaFuncSetAttribute(gemm_tc_kernel, cudaFuncAttributeMaxDynamicSharedMemorySize, GEMM_SMEM);
    cudaFuncSetAttribute(attn_tc_kernel<true>,  cudaFuncAttributeMaxDynamicSharedMemorySize, ATTN_SMEM_TC);
    cudaFuncSetAttribute(attn_tc_kernel<false>, cudaFuncAttributeMaxDynamicSharedMemorySize, ATTN_SMEM_TC);

    // ---- convert weights + encoded to tf32; interleave wi0/wi1 ----
    ConvArgs ca;
    ca.src[0]  = (const float4*)sa_wq;  ca.src[1]  = (const float4*)sa_wk;
    ca.src[2]  = (const float4*)sa_wv;  ca.src[3]  = (const float4*)sa_wo;
    ca.src[4]  = (const float4*)ca_wq;  ca.src[5]  = (const float4*)ca_wk;
    ca.src[6]  = (const float4*)ca_wv;  ca.src[7]  = (const float4*)ca_wo;
    ca.src[8]  = (const float4*)wo;     ca.src[9]  = (const float4*)awd;
    ca.src[10] = (const float4*)awu;    ca.src[11] = (const float4*)encoded;
    conv_kernel<<<(CONV_TOT4 + 255) / 256, 256>>>(ca, wtf);
    ilv_kernel<<<(D_ * F_ + 255) / 256, 256>>>(wi0, wi1, wtf + WI0o);

    const float qscale = 0.125f;   // HD^-0.5
    const float* enc_tf = wtf + ENCo;

    // ---- self attention ----
    rmsnorm_kernel<<<M_, 256>>>(inputs, ln1, xn);
    gemm(xn, wtf + WQ0o, q,  M_, D_, D_, qscale, 0, 0, 0, 0, 0, 1, 0, 0, 0,  0, 0, 0, 0, 0, 1);
    gemm(xn, wtf + WK0o, kc, M_, D_, D_, 1.0f,   0, 0, 0, 0, 0, 1, 0, P_, L_, 0, 0, 0, 0, 0, 1);
    gemm(xn, wtf + WV0o, vc, M_, D_, D_, 1.0f,   0, 0, 0, 0, 0, 1, 0, P_, L_, 0, 0, 0, 0, 0, 1);
    prefix_kernel<<<dim3((P_ * D_ + 255) / 256, B_), 256>>>(pk, pv, kc, vc, 0);
    biastab_kernel<<<(H_ * L_ + 255) / 256, 256>>>(relpos, bt);
    attn_tc_kernel<true><<<dim3(L_ / 64, H_, B_), 128, ATTN_SMEM_TC>>>(q, kc, vc, o, bt);
    gemm(o, wtf + WO0o, x, M_, D_, D_, 1.0f, 0, 0, inputs, 0, 0, 0, 0, 0, 0, 0, 0, 0, 0, 0, 1);

    // ---- cross attention ----
    rmsnorm_kernel<<<M_, 256>>>(x, ln2, xn);
    gemm(xn,     wtf + WQ1o, q,  M_, D_, D_, qscale, 0, 0, 0, 0, 0, 1, 0, 0, 0,  0, 0, 0, 0, 0, 1);
    gemm(enc_tf, wtf + WK1o, kc, M_, D_, D_, 1.0f,   0, 0, 0, 0, 0, 1, 0, P_, L_, 0, 0, 0, 0, 0, 1);
    gemm(enc_tf, wtf + WV1o, vc, M_, D_, D_, 1.0f,   0, 0, 0, 0, 0, 1, 0, P_, L_, 0, 0, 0, 0, 0, 1);
    prefix_kernel<<<dim3((P_ * D_ + 255) / 256, B_), 256>>>(pk, pv, kc, vc, 1);
    attn_tc_kernel<false><<<dim3(L_ / 64, H_, B_), 128, ATTN_SMEM_TC>>>(q, kc, vc, o, 0);
    gemm(o, wtf + WO1o, y, M_, D_, D_, 1.0f, 0, 0, x, 0, 0, 0, 0, 0, 0, 0, 0, 0, 0, 0, 1);

    // ---- fused gated MLP + adapter ----
    rmsnorm_kernel<<<M_, 256>>>(y, ln3, xn);   // xn = lz (tf32-rounded)
    gemm(xn, wtf + WI0o, h1, M_, 2 * F_, D_, 1.0f, 0, 0, 0, 0, 0, 0, 1, 0, 0,
         0, 0, 0, 0, 0, 1);                                        // h1 = roundtf((lz@wi1)*roundtf(gelu(lz@wi0)))
    gemm(h1, wtf + WOMo, out, M_, D_, F_, 1.0f, 0, 0, y, 0, 0, 0, 0, 0, 0, 0, 0, 0, 0, 0, 1);

    // adapter: az = gelu(lz @ wd + bd) (rounded);  out += az @ wu + bu
    gemm(xn, wtf + AWDo, az, L_, A_, D_, 1.0f, abd, 0, 0, 1, 0, 1, 0, 0, 0,
         (long long)L_ * D_, (long long)D_ * A_, (long long)L_ * A_, A_, 0, B_);
    gemm(az, wtf + AWUo, out, L_, D_, A_, 1.0f, abu, 0, 0, 0, 1, 0, 0, 0, 0,
         (long long)L_ * A_, (long long)A_ * D_, (long long)L_ * D_, D_, 0, B_);
}

// round 15
// speedup vs baseline: 1.0846x; 1.0152x over previous
#include <cuda_runtime.h>
#include <math.h>
#include <stdint.h>

#define D_  1024
#define H_  16
#define HD_ 64
#define F_  2816
#define A_  64
#define P_  30
#define NB_ 32
#define B_  4
#define L_  1024
#define LK_ 1054            // P_ + L_
#define M_  4096            // B_ * L_

// ---------------- scratch (device globals; no runtime allocation) ----------------
__device__ float g_xn[M_ * D_];
__device__ float g_q [M_ * D_];
__device__ float g_kc[B_ * LK_ * D_];
__device__ float g_vc[B_ * LK_ * D_];
__device__ float g_o [M_ * D_];
__device__ float g_x [M_ * D_];
__device__ float g_y [M_ * D_];
__device__ float g_h1[(size_t)M_ * F_];
__device__ float g_az[B_ * L_ * A_];
__device__ float g_bt[H_ * L_];
__device__ float g_wtf[21757952];      // tf32-rounded weights + encoded

// float offsets into g_wtf
#define WQKV0o 0             // packed QKV block 0: [D, 3072] (wq*0.125 | wk | wv)
#define WO0o   3145728
#define WQ1o   4194304       // cross-attn wq (flat [D,1024], pre-scaled)
#define WKV1o  5242880       // packed KV block 1: [D, 2048] (wk | wv)
#define WO1o   7340032
#define WI0o   8388608       // packed gated-MLP weights [D, 5632]
#define WOMo   14155776
#define AWDo   17039360
#define AWUo   17301504
#define ENCo   17563648

// ---------------- helpers ----------------
__device__ __forceinline__ float gelu_f(float x) {
    const float c = 0.7978845608028654f;       // sqrt(2/pi)
    float t = tanhf(c * (x + 0.044715f * x * x * x));
    return 0.5f * x * (1.0f + t);
}

__device__ __forceinline__ unsigned f2tf(float f) {
    unsigned u;
    asm("cvt.rna.tf32.f32 %0, %1;" : "=r"(u) : "f"(f));
    return u;
}
__device__ __forceinline__ float roundtf(float f) { return __uint_as_float(f2tf(f)); }

__device__ __forceinline__ void mma8(float* c, const unsigned* a, unsigned b0, unsigned b1) {
    asm volatile(
        "mma.sync.aligned.m16n8k8.row.col.f32.tf32.tf32.f32 "
        "{%0,%1,%2,%3},{%4,%5,%6,%7},{%8,%9},{%0,%1,%2,%3};"
        : "+f"(c[0]), "+f"(c[1]), "+f"(c[2]), "+f"(c[3])
        : "r"(a[0]), "r"(a[1]), "r"(a[2]), "r"(a[3]), "r"(b0), "r"(b1));
}

__device__ __forceinline__ void ldsm4(unsigned& r0, unsigned& r1, unsigned& r2, unsigned& r3,
                                      uint32_t addr) {
    asm volatile("ldmatrix.sync.aligned.m8n8.x4.shared.b16 {%0,%1,%2,%3}, [%4];"
                 : "=r"(r0), "=r"(r1), "=r"(r2), "=r"(r3) : "r"(addr));
}

__device__ __forceinline__ uint32_t smem_u32(const void* p) {
    uint32_t a;
    asm("{ .reg .u64 t; cvta.to.shared.u64 t, %1; cvt.u32.u64 %0, t; }" : "=r"(a) : "l"(p));
    return a;
}

// ---------------- weight/encoded tf32 conversion (6 flat sources) ----------------
struct ConvArgs { const float4* src[6]; };
#define CONV_TOT4 2424832

__global__ void conv_kernel(ConvArgs a, float* __restrict__ wtf) {
    static const int cum[7] = {0, 262144, 524288, 1245184, 1310720, 1376256, 2424832};
    static const int dstoff4[6] = {WO0o / 4, WO1o / 4, WOMo / 4,
                                   AWDo / 4, AWUo / 4, ENCo / 4};
    int t = blockIdx.x * 256 + threadIdx.x;
    if (t >= CONV_TOT4) return;
    int j = 0;
    #pragma unroll
    for (int k = 1; k < 6; ++k) if (t >= cum[k]) j = k;
    float4 v = a.src[j][t - cum[j]];
    v.x = roundtf(v.x); v.y = roundtf(v.y); v.z = roundtf(v.z); v.w = roundtf(v.w);
    ((float4*)wtf)[dstoff4[j] + (t - cum[j])] = v;
}

// ---------------- QKV pack: dst[k][3072] = [wq*0.125 | wk | wv] (tf32-rounded) ----------
__global__ void qkvpack_kernel(const float* __restrict__ wq, const float* __restrict__ wk,
                               const float* __restrict__ wv, float* __restrict__ dst) {
    int i = blockIdx.x * 256 + threadIdx.x;
    if (i >= D_ * 3072) return;
    int k = i / 3072, j = i % 3072;
    int seg = j >> 10, n = j & 1023;
    float v;
    if (seg == 0)      v = wq[k * D_ + n] * 0.125f;   // exact 2^-3 pre-scale
    else if (seg == 1) v = wk[k * D_ + n];
    else               v = wv[k * D_ + n];
    dst[i] = roundtf(v);
}

// ---------------- KV pack (cross-attn): dst[k][2048] = [wk | wv]; plus wq*0.125 flat ----
__global__ void kvpack_kernel(const float* __restrict__ wq, const float* __restrict__ wk,
                              const float* __restrict__ wv,
                              float* __restrict__ dstq, float* __restrict__ dstkv) {
    int i = blockIdx.x * 256 + threadIdx.x;
    if (i >= D_ * 2048) return;
    int k = i / 2048, j = i % 2048;
    int seg = j >> 10, n = j & 1023;
    dstkv[i] = roundtf(seg == 0 ? wk[k * D_ + n] : wv[k * D_ + n]);
    if (seg == 0) dstq[k * D_ + n] = roundtf(wq[k * D_ + n] * 0.125f);
}

// ---------------- wi0/wi1 interleave + round ----------------
__global__ void ilv_kernel(const float* __restrict__ w0, const float* __restrict__ w1,
                           float* __restrict__ dst) {
    int i = blockIdx.x * 256 + threadIdx.x;
    if (i >= D_ * F_) return;
    int k = i / F_, j = i % F_;
    size_t base = (size_t)k * (2 * F_) + ((j >> 3) << 4) + (j & 7);
    dst[base]     = roundtf(w0[i]);
    dst[base + 8] = roundtf(w1[i]);
}

// ---------------- rmsnorm (tf32-rounded output) ----------------
__global__ void rmsnorm_kernel(const float* __restrict__ x,
                               const float* __restrict__ sc,
                               float* __restrict__ out) {
    int row = blockIdx.x;
    int t = threadIdx.x;
    const float4* xr = (const float4*)(x + (size_t)row * D_);
    float4 v = xr[t];
    float ss = v.x * v.x + v.y * v.y + v.z * v.z + v.w * v.w;
    #pragma unroll
    for (int o = 16; o; o >>= 1) ss += __shfl_xor_sync(0xffffffffu, ss, o);
    __shared__ float sred[8];
    if ((t & 31) == 0) sred[t >> 5] = ss;
    __syncthreads();
    if (t < 8) {
        float s2 = sred[t];
        #pragma unroll
        for (int o = 4; o; o >>= 1) s2 += __shfl_xor_sync(0xffu, s2, o);
        if (t == 0) sred[0] = s2;
    }
    __syncthreads();
    float inv = rsqrtf(sred[0] * (1.0f / D_) + 1e-6f);
    float4 sv = ((const float4*)sc)[t];
    float4 ov = make_float4(roundtf(v.x * inv * sv.x), roundtf(v.y * inv * sv.y),
                            roundtf(v.z * inv * sv.z), roundtf(v.w * inv * sv.w));
    ((float4*)(out + (size_t)row * D_))[t] = ov;
}

// ---------------- tf32 tensor-core GEMM ----------------
// Modes: normal / gate_pack / qkv (route 1024-col segments to C,Ck,Cv; segs >=1 kv-padded).
#define GBM 128
#define GBN 128
#define GBK 32
#define PIT 36
#define TILEF (128 * PIT)
#define GEMM_SMEM (4 * TILEF * 4)

__global__ __launch_bounds__(256, 2)
void gemm_tc_kernel(const float* __restrict__ A, const float* __restrict__ Bm,
                    float* __restrict__ C, int M, int N, int K,
                    float alpha,
                    const float* __restrict__ bias,
                    const float* __restrict__ mulin,
                    const float* __restrict__ residual,
                    float* __restrict__ Ck, float* __restrict__ Cv, int qkv,
                    int do_gelu, int accumulate, int round_out, int gate_pack,
                    int kv_pad, int seg_rows,
                    long long sA, long long sB, long long sC,
                    long long sBias, long long sRes) {
    int z = blockIdx.z;
    A  += (size_t)z * sA;
    Bm += (size_t)z * sB;
    C  += (size_t)z * sC;
    if (bias)     bias     += (size_t)z * sBias;
    if (residual) residual += (size_t)z * sRes;

    extern __shared__ __align__(16) float sm[];

    int tid  = threadIdx.x;
    int lane = tid & 31;
    int wid  = tid >> 5;
    int grpr = lane >> 2;
    int grpc = lane & 3;
    int warp_m = (wid & 1) * 64;
    int warp_n = (wid >> 1) * 32;
    int bm = blockIdx.y * GBM;
    int bn = blockIdx.x * GBN;

    int ar = tid >> 2;
    int ac = (tid & 3) * 8;
    int nB = tid & 127;
    int kh = (tid >> 7) * 16;
    int bok = (bn + nB < N);
    const float* Bp = Bm + (bok ? bn + nB : 0);

    uint32_t smB = smem_u32(sm);
    uint32_t aLane = smB + (((lane & 15) * PIT + (lane >> 4) * 4) + warp_m * PIT) * 4u;
    uint32_t bLane = smB + 2u * TILEF * 4u
                   + (((warp_n + (lane & 7) + ((lane >> 4) * 8)) * PIT
                       + ((lane >> 3) & 1) * 4)) * 4u;

    float acc[4][4][4];
    #pragma unroll
    for (int i = 0; i < 4; ++i)
        #pragma unroll
        for (int j = 0; j < 4; ++j)
            #pragma unroll
            for (int k = 0; k < 4; ++k) acc[i][j][k] = 0.0f;

    int ntiles = K / GBK;
    float4 aR[4], bR[4];

    {
        const float* Ap = A + (size_t)(bm + ar) * K + ac;
        aR[0] = *(const float4*)Ap;
        aR[1] = *(const float4*)(Ap + 4);
        aR[2] = *(const float4*)(Ap + (size_t)64 * K);
        aR[3] = *(const float4*)(Ap + (size_t)64 * K + 4);
        if (bok) {
            #pragma unroll
            for (int i = 0; i < 4; ++i) {
                bR[i].x = Bp[(size_t)(kh + 4 * i + 0) * N];
                bR[i].y = Bp[(size_t)(kh + 4 * i + 1) * N];
                bR[i].z = Bp[(size_t)(kh + 4 * i + 2) * N];
                bR[i].w = Bp[(size_t)(kh + 4 * i + 3) * N];
            }
        } else {
            #pragma unroll
            for (int i = 0; i < 4; ++i) bR[i] = make_float4(0.f, 0.f, 0.f, 0.f);
        }
        float* As0 = sm;
        float* Bs0 = sm + 2 * TILEF;
        *(float4*)&As0[ar * PIT + ac]            = aR[0];
        *(float4*)&As0[ar * PIT + ac + 4]        = aR[1];
        *(float4*)&As0[(ar + 64) * PIT + ac]     = aR[2];
        *(float4*)&As0[(ar + 64) * PIT + ac + 4] = aR[3];
        #pragma unroll
        for (int i = 0; i < 4; ++i)
            *(float4*)&Bs0[nB * PIT + kh + 4 * i] = bR[i];
    }
    __syncthreads();

    for (int kt = 0; kt < ntiles; ++kt) {
        if (kt + 1 < ntiles) {
            const float* Ap = A + (size_t)(bm + ar) * K + (kt + 1) * GBK + ac;
            aR[0] = *(const float4*)Ap;
            aR[1] = *(const float4*)(Ap + 4);
            aR[2] = *(const float4*)(Ap + (size_t)64 * K);
            aR[3] = *(const float4*)(Ap + (size_t)64 * K + 4);
            if (bok) {
                const float* Bn = Bp + (size_t)(kt + 1) * GBK * N;
                #pragma unroll
                for (int i = 0; i < 4; ++i) {
                    bR[i].x = Bn[(size_t)(kh + 4 * i + 0) * N];
                    bR[i].y = Bn[(size_t)(kh + 4 * i + 1) * N];
                    bR[i].z = Bn[(size_t)(kh + 4 * i + 2) * N];
                    bR[i].w = Bn[(size_t)(kh + 4 * i + 3) * N];
                }
            }
        }
        uint32_t aBuf = aLane + (uint32_t)(kt & 1) * TILEF * 4u;
        uint32_t bBuf = bLane + (uint32_t)(kt & 1) * TILEF * 4u;
        #pragma unroll
        for (int ks = 0; ks < 4; ++ks) {
            unsigned af[4][4];
            #pragma unroll
            for (int ma = 0; ma < 4; ++ma)
                ldsm4(af[ma][0], af[ma][1], af[ma][2], af[ma][3],
                      aBuf + (uint32_t)((ma * 16 * PIT + ks * 8) * 4));
            #pragma unroll
            for (int p = 0; p < 2; ++p) {
                unsigned kb[4];
                ldsm4(kb[0], kb[1], kb[2], kb[3],
                      bBuf + (uint32_t)((p * 16 * PIT + ks * 8) * 4));
                #pragma unroll
                for (int ma = 0; ma < 4; ++ma) {
                    mma8(acc[ma][2 * p + 0], af[ma], kb[0], kb[1]);
                    mma8(acc[ma][2 * p + 1], af[ma], kb[2], kb[3]);
                }
            }
        }
        if (kt + 1 < ntiles) {
            float* ad = sm + ((kt + 1) & 1) * TILEF;
            float* bd = sm + 2 * TILEF + ((kt + 1) & 1) * TILEF;
            *(float4*)&ad[ar * PIT + ac]            = aR[0];
            *(float4*)&ad[ar * PIT + ac + 4]        = aR[1];
            *(float4*)&ad[(ar + 64) * PIT + ac]     = aR[2];
            *(float4*)&ad[(ar + 64) * PIT + ac + 4] = aR[3];
            #pragma unroll
            for (int i = 0; i < 4; ++i)
                *(float4*)&bd[nB * PIT + kh + 4 * i] = bR[i];
            __syncthreads();
        }
    }

    if (qkv) {
        // 1024-col segments routed to C / Ck / Cv; segments >= qkv_first_pad are kv-padded.
        int seg = bn >> 10;
        float* dst;
        int pad;
        if (qkv == 1) {        // [q | k | v]
            dst = (seg == 0) ? C : (seg == 1 ? Ck : Cv);
            pad = (seg != 0);
        } else {               // qkv == 2: [k | v]
            dst = (seg == 0) ? Ck : Cv;
            pad = 1;
        }
        int nbase = bn & 1023;
        #pragma unroll
        for (int ma = 0; ma < 4; ++ma) {
            #pragma unroll
            for (int na = 0; na < 4; ++na) {
                int n = nbase + warp_n + na * 8 + 2 * grpc;
                #pragma unroll
                for (int half = 0; half < 2; ++half) {
                    int m = bm + warp_m + ma * 16 + grpr + half * 8;
                    long long orow = m;
                    if (pad) orow = (long long)m + (long long)P_ * (m / L_ + 1);
                    float v0 = roundtf(acc[ma][na][half * 2 + 0]);
                    float v1 = roundtf(acc[ma][na][half * 2 + 1]);
                    *(float2*)(dst + (size_t)orow * 1024 + n) = make_float2(v0, v1);
                }
            }
        }
        return;
    }

    if (gate_pack) {
        int Nout = N >> 1;
        #pragma unroll
        for (int ma = 0; ma < 4; ++ma) {
            #pragma unroll
            for (int p = 0; p < 2; ++p) {
                int outn = ((bn + warp_n) >> 1) + p * 8 + 2 * grpc;
                #pragma unroll
                for (int half = 0; half < 2; ++half) {
                    int m = bm + warp_m + ma * 16 + grpr + half * 8;
                    float g0 = roundtf(gelu_f(acc[ma][2 * p][half * 2 + 0]));
                    float g1 = roundtf(gelu_f(acc[ma][2 * p][half * 2 + 1]));
                    float v0 = roundtf(acc[ma][2 * p + 1][half * 2 + 0] * g0);
                    float v1 = roundtf(acc[ma][2 * p + 1][half * 2 + 1] * g1);
                    *(float2*)(C + (size_t)m * Nout + outn) = make_float2(v0, v1);
                }
            }
        }
        return;
    }

    #pragma unroll
    for (int ma = 0; ma < 4; ++ma) {
        #pragma unroll
        for (int na = 0; na < 4; ++na) {
            int n = bn + warp_n + na * 8 + 2 * grpc;
            if (n >= N) continue;
            #pragma unroll
            for (int half = 0; half < 2; ++half) {
                int m = bm + warp_m + ma * 16 + grpr + half * 8;
                float v0 = alpha * acc[ma][na][half * 2 + 0];
                float v1 = alpha * acc[ma][na][half * 2 + 1];
                if (bias) { v0 += bias[n]; v1 += bias[n + 1]; }
                if (do_gelu) { v0 = gelu_f(v0); v1 = gelu_f(v1); }
                if (mulin) {
                    float2 mv = *(const float2*)(mulin + (size_t)m * N + n);
                    v0 *= mv.x; v1 *= mv.y;
                }
                if (residual) {
                    float2 rv = *(const float2*)(residual + (size_t)m * N + n);
                    v0 += rv.x; v1 += rv.y;
                }
                long long orow = m;
                if (kv_pad) orow = (long long)m + (long long)kv_pad * (m / seg_rows + 1);
                float* cp = C + (size_t)orow * N + n;
                if (accumulate) {
                    float2 cv = *(const float2*)cp;
                    v0 += cv.x; v1 += cv.y;
                }
                if (round_out) { v0 = roundtf(v0); v1 = roundtf(v1); }
                *(float2*)cp = make_float2(v0, v1);
            }
        }
    }
}

// ---------------- relative position bias table ----------------
__global__ void biastab_kernel(const float* __restrict__ relpos, float* __restrict__ tab) {
    int idx = blockIdx.x * 256 + threadIdx.x;
    if (idx >= H_ * L_) return;
    int h = idx / L_, rel = idx % L_;
    int bucket;
    if (rel < 16) {
        bucket = rel;
    } else {
        float lg = logf((float)rel * (1.0f / 16.0f)) * (16.0f / 2.0794415416798357f);
        bucket = 16 + (int)lg;
        if (bucket > 31) bucket = 31;
    }
    tab[idx] = relpos[h * NB_ + bucket];
}

// ---------------- prefix KV copy (tf32-rounded) ----------------
__global__ void prefix_kernel(const float* __restrict__ pk, const float* __restrict__ pv,
                              float* __restrict__ kc, float* __restrict__ vc, int sel) {
    int b = blockIdx.y;
    int i = blockIdx.x * 256 + threadIdx.x;
    if (i >= P_ * D_) return;
    size_t src = ((size_t)(b * 2 + sel)) * (P_ * D_) + i;
    size_t dst = (size_t)b * LK_ * D_ + i;
    kc[dst] = roundtf(pk[src]);
    vc[dst] = roundtf(pv[src]);
}

// ---------------- tensor-core flash attention (LDSM for Q/K/P fragments) --------------
#define ATTN_SMEM_TC ((64 * 68 + 64 * 72 + 64 * 68) * 4 + L_ * 4)

template <bool CAUSAL>
__global__ __launch_bounds__(128)
void attn_tc_kernel(const float* __restrict__ Q, const float* __restrict__ Kc,
                    const float* __restrict__ Vc, float* __restrict__ O,
                    const float* __restrict__ btab) {
    extern __shared__ __align__(16) unsigned smu[];
    unsigned* Ks = smu;                      // [64][68]
    unsigned* Vs = Ks + 64 * 68;             // [64][72]
    unsigned* Ps = Vs + 64 * 72;             // [64][68]
    float* bsh = (float*)(Ps + 64 * 68);     // [1024]

    int q0 = blockIdx.x * 64;
    int h  = blockIdx.y;
    int b  = blockIdx.z;
    int tid  = threadIdx.x;
    int w    = tid >> 5;
    int lane = tid & 31;
    int grpr = lane >> 2;
    int grpc = lane & 3;

    const float* Qb = Q  + (size_t)(b * L_)  * D_ + h * HD_;
    const float* Kb = Kc + (size_t)(b * LK_) * D_ + h * HD_;
    const float* Vb = Vc + (size_t)(b * LK_) * D_ + h * HD_;

    uint32_t ksU = smem_u32(Ks);
    uint32_t psU = smem_u32(Ps);
    uint32_t laneA = (((lane & 15) * 68 + (lane >> 4) * 4)) * 4u;
    uint32_t laneK = ((((lane & 7) + (lane >> 4) * 8) * 68 + ((lane >> 3) & 1) * 4)) * 4u;

    for (int i = tid; i < 64 * 16; i += 128) {
        int r = i >> 4, c4 = i & 15;
        float4 v = *(const float4*)(Qb + (size_t)(q0 + r) * D_ + c4 * 4);
        *(float4*)&Ks[r * 68 + c4 * 4] = v;
    }
    if (CAUSAL) {
        for (int i = tid; i < L_; i += 128) bsh[i] = btab[h * L_ + i];
    }
    __syncthreads();

    unsigned qa[8][4];
    {
        uint32_t qBase = ksU + laneA + (uint32_t)(w * 16 * 68 * 4);
        #pragma unroll
        for (int ks = 0; ks < 8; ++ks)
            ldsm4(qa[ks][0], qa[ks][1], qa[ks][2], qa[ks][3], qBase + ks * 32u);
    }

    float m0r = -1e30f, m1r = -1e30f, l0 = 0.0f, l1 = 0.0f;
    float oacc[8][4];
    #pragma unroll
    for (int na = 0; na < 8; ++na)
        #pragma unroll
        for (int k = 0; k < 4; ++k) oacc[na][k] = 0.0f;

    int r0g = q0 + w * 16 + grpr;
    int r1g = r0g + 8;

    int ntiles = (LK_ + 63) / 64;
    if (CAUSAL) {
        int need = blockIdx.x + 2;
        if (need < ntiles) ntiles = need;
    }

    for (int kt = 0; kt < ntiles; ++kt) {
        int k0 = kt * 64;
        __syncthreads();
        for (int i = tid; i < 64 * 16; i += 128) {
            int r = i >> 4, c4 = i & 15;
            int j = k0 + r;
            float4 kv, vv;
            if (j < LK_) {
                kv = *(const float4*)(Kb + (size_t)j * D_ + c4 * 4);
                vv = *(const float4*)(Vb + (size_t)j * D_ + c4 * 4);
            } else {
                kv = make_float4(0.f, 0.f, 0.f, 0.f);
                vv = kv;
            }
            *(float4*)&Ks[r * 68 + c4 * 4] = kv;
            *(float4*)&Vs[r * 72 + c4 * 4] = vv;
        }
        __syncthreads();

        float sacc[8][4];
        #pragma unroll
        for (int na = 0; na < 8; ++na)
            #pragma unroll
            for (int k = 0; k < 4; ++k) sacc[na][k] = 0.0f;
        uint32_t kBase = ksU + laneK;
        #pragma unroll
        for (int ks = 0; ks < 8; ++ks) {
            #pragma unroll
            for (int nap = 0; nap < 4; ++nap) {
                unsigned kb[4];
                ldsm4(kb[0], kb[1], kb[2], kb[3],
                      kBase + (uint32_t)((nap * 16 * 68 + ks * 8) * 4));
                mma8(sacc[2 * nap + 0], qa[ks], kb[0], kb[1]);
                mma8(sacc[2 * nap + 1], qa[ks], kb[2], kb[3]);
            }
        }

        float rm0 = -1e30f, rm1 = -1e30f;
        #pragma unroll
        for (int na = 0; na < 8; ++na) {
            int j0 = k0 + na * 8 + 2 * grpc;
            int j1 = j0 + 1;
            if (CAUSAL) {
                if (j0 >= P_) {
                    int kp = j0 - P_;
                    if (kp > r0g) sacc[na][0] = -1e30f; else sacc[na][0] += bsh[r0g - kp];
                    if (kp > r1g) sacc[na][2] = -1e30f; else sacc[na][2] += bsh[r1g - kp];
                }
                if (j1 >= P_) {
                    int kp = j1 - P_;
                    if (kp > r0g) sacc[na][1] = -1e30f; else sacc[na][1] += bsh[r0g - kp];
                    if (kp > r1g) sacc[na][3] = -1e30f; else sacc[na][3] += bsh[r1g - kp];
                }
            } else {
                if (j0 >= LK_) { sacc[na][0] = -1e30f; sacc[na][2] = -1e30f; }
                if (j1 >= LK_) { sacc[na][1] = -1e30f; sacc[na][3] = -1e30f; }
            }
            rm0 = fmaxf(rm0, fmaxf(sacc[na][0], sacc[na][1]));
            rm1 = fmaxf(rm1, fmaxf(sacc[na][2], sacc[na][3]));
        }
        rm0 = fmaxf(rm0, __shfl_xor_sync(0xffffffffu, rm0, 1));
        rm0 = fmaxf(rm0, __shfl_xor_sync(0xffffffffu, rm0, 2));
        rm1 = fmaxf(rm1, __shfl_xor_sync(0xffffffffu, rm1, 1));
        rm1 = fmaxf(rm1, __shfl_xor_sync(0xffffffffu, rm1, 2));

        float mn0 = fmaxf(m0r, rm0);
        float mn1 = fmaxf(m1r, rm1);
        float cf0 = __expf(m0r - mn0);
        float cf1 = __expf(m1r - mn1);
        l0 *= cf0; l1 *= cf1;
        m0r = mn0; m1r = mn1;
        #pragma unroll
        for (int na = 0; na < 8; ++na) {
            oacc[na][0] *= cf0; oacc[na][1] *= cf0;
            oacc[na][2] *= cf1; oacc[na][3] *= cf1;
        }

        float ps0 = 0.0f, ps1 = 0.0f;
        int pr = w * 16 + grpr;
        #pragma unroll
        for (int na = 0; na < 8; ++na) {
            float p0 = __expf(sacc[na][0] - mn0);
            float p1 = __expf(sacc[na][1] - mn0);
            float p2 = __expf(sacc[na][2] - mn1);
            float p3 = __expf(sacc[na][3] - mn1);
            ps0 += p0 + p1;
            ps1 += p2 + p3;
            uint2 u01; u01.x = f2tf(p0); u01.y = f2tf(p1);
            uint2 u23; u23.x = f2tf(p2); u23.y = f2tf(p3);
            *(uint2*)&Ps[pr * 68 + na * 8 + 2 * grpc]       = u01;
            *(uint2*)&Ps[(pr + 8) * 68 + na * 8 + 2 * grpc] = u23;
        }
        ps0 += __shfl_xor_sync(0xffffffffu, ps0, 1);
        ps0 += __shfl_xor_sync(0xffffffffu, ps0, 2);
        ps1 += __shfl_xor_sync(0xffffffffu, ps1, 1);
        ps1 += __shfl_xor_sync(0xffffffffu, ps1, 2);
        l0 += ps0; l1 += ps1;

        __syncwarp();

        uint32_t pBase = psU + laneA + (uint32_t)(w * 16 * 68 * 4);
        #pragma unroll
        for (int ks = 0; ks < 8; ++ks) {
            unsigned pa[4];
            ldsm4(pa[0], pa[1], pa[2], pa[3], pBase + ks * 32u);
            #pragma unroll
            for (int na = 0; na < 8; ++na) {
                unsigned b0 = Vs[(ks * 8 + grpc) * 72 + na * 8 + grpr];
                unsigned b1 = Vs[(ks * 8 + 4 + grpc) * 72 + na * 8 + grpr];
                mma8(oacc[na], pa, b0, b1);
            }
        }
    }

    float inv0 = 1.0f / l0;
    float inv1 = 1.0f / l1;
    float* Ob = O + (size_t)(b * L_) * D_ + h * HD_;
    int qr0 = q0 + w * 16 + grpr;
    #pragma unroll
    for (int na = 0; na < 8; ++na) {
        int d = na * 8 + 2 * grpc;
        *(float2*)(Ob + (size_t)qr0 * D_ + d) =
            make_float2(roundtf(oacc[na][0] * inv0), roundtf(oacc[na][1] * inv0));
        *(float2*)(Ob + (size_t)(qr0 + 8) * D_ + d) =
            make_float2(roundtf(oacc[na][2] * inv1), roundtf(oacc[na][3] * inv1));
    }
}

// ---------------- host side ----------------
static void gemm_full(const float* A, const float* Bm, float* C, int M, int N, int K,
                      float alpha, const float* bias, const float* mulin,
                      const float* residual, float* Ck, float* Cv, int qkv,
                      int do_gelu, int accumulate, int round_out, int gate_pack,
                      int kv_pad, int seg_rows,
                      long long sA, long long sB, long long sC,
                      long long sBias, long long sRes, int batches) {
    dim3 grid((N + GBN - 1) / GBN, (M + GBM - 1) / GBM, batches);
    gemm_tc_kernel<<<grid, 256, GEMM_SMEM>>>(A, Bm, C, M, N, K, alpha, bias, mulin,
                                             residual, Ck, Cv, qkv,
                                             do_gelu, accumulate, round_out,
                                             gate_pack, kv_pad, seg_rows,
                                             sA, sB, sC, sBias, sRes);
}

static void gemm(const float* A, const float* Bm, float* C, int M, int N, int K,
                 float alpha, const float* bias, const float* mulin,
                 const float* residual,
                 int do_gelu, int accumulate, int round_out, int gate_pack,
                 int kv_pad, int seg_rows,
                 long long sA, long long sB, long long sC,
                 long long sBias, long long sRes, int batches) {
    gemm_full(A, Bm, C, M, N, K, alpha, bias, mulin, residual, 0, 0, 0,
              do_gelu, accumulate, round_out, gate_pack, kv_pad, seg_rows,
              sA, sB, sC, sBias, sRes, batches);
}

extern "C" void kernel_launch(void* const* d_in, const int* in_sizes, int n_in,
                              void* d_out, int out_size) {
    const float* inputs  = (const float*)d_in[0];
    const float* encoded = (const float*)d_in[1];
    const float* awd     = (const float*)d_in[2];
    const float* awu     = (const float*)d_in[3];
    const float* abd     = (const float*)d_in[4];
    const float* abu     = (const float*)d_in[5];
    const float* pk      = (const float*)d_in[6];
    const float* pv      = (const float*)d_in[7];
    const float* ln1     = (const float*)d_in[8];
    const float* ln2     = (const float*)d_in[9];
    const float* ln3     = (const float*)d_in[10];
    const float* sa_wq   = (const float*)d_in[11];
    const float* sa_wk   = (const float*)d_in[12];
    const float* sa_wv   = (const float*)d_in[13];
    const float* sa_wo   = (const float*)d_in[14];
    const float* ca_wq   = (const float*)d_in[15];
    const float* ca_wk   = (const float*)d_in[16];
    const float* ca_wv   = (const float*)d_in[17];
    const float* ca_wo   = (const float*)d_in[18];
    const float* relpos  = (const float*)d_in[19];
    const float* wi0     = (const float*)d_in[20];
    const float* wi1     = (const float*)d_in[21];
    const float* wo      = (const float*)d_in[22];
    float* out = (float*)d_out;

    float *xn, *q, *kc, *vc, *o, *x, *y, *h1, *az, *bt, *wtf;
    cudaGetSymbolAddress((void**)&xn, g_xn);
    cudaGetSymbolAddress((void**)&q,  g_q);
    cudaGetSymbolAddress((void**)&kc, g_kc);
    cudaGetSymbolAddress((void**)&vc, g_vc);
    cudaGetSymbolAddress((void**)&o,  g_o);
    cudaGetSymbolAddress((void**)&x,  g_x);
    cudaGetSymbolAddress((void**)&y,  g_y);
    cudaGetSymbolAddress((void**)&h1, g_h1);
    cudaGetSymbolAddress((void**)&az, g_az);
    cudaGetSymbolAddress((void**)&bt, g_bt);
    cudaGetSymbolAddress((void**)&wtf, g_wtf);

    cudaFuncSetAttribute(gemm_tc_kernel, cudaFuncAttributeMaxDynamicSharedMemorySize, GEMM_SMEM);
    cudaFuncSetAttribute(attn_tc_kernel<true>,  cudaFuncAttributeMaxDynamicSharedMemorySize, ATTN_SMEM_TC);
    cudaFuncSetAttribute(attn_tc_kernel<false>, cudaFuncAttributeMaxDynamicSharedMemorySize, ATTN_SMEM_TC);

    // ---- weight prep ----
    ConvArgs ca;
    ca.src[0] = (const float4*)sa_wo;  ca.src[1] = (const float4*)ca_wo;
    ca.src[2] = (const float4*)wo;     ca.src[3] = (const float4*)awd;
    ca.src[4] = (const float4*)awu;    ca.src[5] = (const float4*)encoded;
    conv_kernel<<<(CONV_TOT4 + 255) / 256, 256>>>(ca, wtf);
    qkvpack_kernel<<<(D_ * 3072 + 255) / 256, 256>>>(sa_wq, sa_wk, sa_wv, wtf + WQKV0o);
    kvpack_kernel<<<(D_ * 2048 + 255) / 256, 256>>>(ca_wq, ca_wk, ca_wv,
                                                    wtf + WQ1o, wtf + WKV1o);
    ilv_kernel<<<(D_ * F_ + 255) / 256, 256>>>(wi0, wi1, wtf + WI0o);

    const float* enc_tf = wtf + ENCo;

    // ---- self attention (fused QKV) ----
    rmsnorm_kernel<<<M_, 256>>>(inputs, ln1, xn);
    gemm_full(xn, wtf + WQKV0o, q, M_, 3072, D_, 1.0f, 0, 0, 0, kc, vc, 1,
              0, 0, 1, 0, 0, 0, 0, 0, 0, 0, 0, 1);
    prefix_kernel<<<dim3((P_ * D_ + 255) / 256, B_), 256>>>(pk, pv, kc, vc, 0);
    biastab_kernel<<<(H_ * L_ + 255) / 256, 256>>>(relpos, bt);
    attn_tc_kernel<true><<<dim3(L_ / 64, H_, B_), 128, ATTN_SMEM_TC>>>(q, kc, vc, o, bt);
    gemm(o, wtf + WO0o, x, M_, D_, D_, 1.0f, 0, 0, inputs, 0, 0, 0, 0, 0, 0, 0, 0, 0, 0, 0, 1);

    // ---- cross attention (fused KV from encoded; Q separate from xn) ----
    rmsnorm_kernel<<<M_, 256>>>(x, ln2, xn);
    gemm_full(enc_tf, wtf + WKV1o, 0, M_, 2048, D_, 1.0f, 0, 0, 0, kc, vc, 2,
              0, 0, 1, 0, 0, 0, 0, 0, 0, 0, 0, 1);
    gemm(xn, wtf + WQ1o, q, M_, D_, D_, 1.0f, 0, 0, 0, 0, 0, 1, 0, 0, 0,
         0, 0, 0, 0, 0, 1);
    prefix_kernel<<<dim3((P_ * D_ + 255) / 256, B_), 256>>>(pk, pv, kc, vc, 1);
    attn_tc_kernel<false><<<dim3(L_ / 64, H_, B_), 128, ATTN_SMEM_TC>>>(q, kc, vc, o, 0);
    gemm(o, wtf + WO1o, y, M_, D_, D_, 1.0f, 0, 0, x, 0, 0, 0, 0, 0, 0, 0, 0, 0, 0, 0, 1);

    // ---- fused gated MLP + adapter ----
    rmsnorm_kernel<<<M_, 256>>>(y, ln3, xn);
    gemm(xn, wtf + WI0o, h1, M_, 2 * F_, D_, 1.0f, 0, 0, 0, 0, 0, 0, 1, 0, 0,
         0, 0, 0, 0, 0, 1);
    gemm(h1, wtf + WOMo, out, M_, D_, F_, 1.0f, 0, 0, y, 0, 0, 0, 0, 0, 0, 0, 0, 0, 0, 0, 1);

    gemm(xn, wtf + AWDo, az, L_, A_, D_, 1.0f, abd, 0, 0, 1, 0, 1, 0, 0, 0,
         (long long)L_ * D_, (long long)D_ * A_, (long long)L_ * A_, A_, 0, B_);
    gemm(az, wtf + AWUo, out, L_, D_, A_, 1.0f, abu, 0, 0, 0, 1, 0, 0, 0, 0,
         (long long)L_ * A_, (long long)A_ * D_, (long long)L_ * D_, D_, 0, B_);
}